// round 13
// baseline (speedup 1.0000x reference)
#include <cuda_runtime.h>
#include <cuda_bf16.h>
#include <cstdint>

#define MAXN   50000
#define KNB    32
#define INC    128
#define H      64
#define EDGED  32
#define H2     128
#define NBMAX  391   // ceil(MAXN/128)

// ---------------- scratch (static device memory; no allocation) ----------------
__device__ float g_src [(size_t)MAXN * H];    // x @ w_src.T
__device__ float g_dst [(size_t)MAXN * H];    // x @ w_dst.T
__device__ float g_out [(size_t)MAXN * H];
__device__ float g_h   [(size_t)MAXN * H2];
__device__ float g_part [2 * NBMAX * H2];
__device__ float g_sb  [2 * H2];

// Prepacked B fragments (bf16 hi/lo split, MMA register layout):
// uint4 = {bh0, bh1, bl0, bl1} per lane.
__device__ uint4 g_bfrag_proj[8 * 16 * 32];   // [k16][jb(16)][lane]
__device__ uint4 g_bfrag_mlp2[8 * 8 * 32];    // [k16][jb(8)][lane]
__device__ uint4 g_bfrag_edge[2 * 8 * 32];    // [ks][j(8)][lane]
__device__ uint4 g_bfrag_mlp1[4 * 16 * 32];   // [k16][jb(16)][lane]

// ---------------- helpers ----------------
// bf16 hi/lo split using the packed cvt: 6 instrs/pair, same rn rounding
// as __float2bfloat16 (bit-identical results, ~40% fewer ALU ops).
__device__ __forceinline__ unsigned pack_split_hi(float a, float b,
                                                  unsigned& lo_pack) {
    unsigned hi;
    asm("cvt.rn.bf16x2.f32 %0, %1, %2;" : "=r"(hi) : "f"(b), "f"(a));
    float ah = __uint_as_float(hi << 16);
    float bh = __uint_as_float(hi & 0xffff0000u);
    float ra = a - ah;
    float rb = b - bh;
    unsigned lo;
    asm("cvt.rn.bf16x2.f32 %0, %1, %2;" : "=r"(lo) : "f"(rb), "f"(ra));
    lo_pack = lo;
    return hi;
}

__device__ __forceinline__ void mma_bf16(float& d0, float& d1, float& d2, float& d3,
                                         unsigned a0, unsigned a1, unsigned a2, unsigned a3,
                                         unsigned b0, unsigned b1) {
    asm volatile(
        "mma.sync.aligned.m16n8k16.row.col.f32.bf16.bf16.f32 "
        "{%0,%1,%2,%3}, {%4,%5,%6,%7}, {%8,%9}, {%0,%1,%2,%3};"
        : "+f"(d0), "+f"(d1), "+f"(d2), "+f"(d3)
        : "r"(a0), "r"(a1), "r"(a2), "r"(a3), "r"(b0), "r"(b1));
}

// =====================================================================
// Kernel P-a: prepack B fragments for proj + mlp1.
// =====================================================================
__global__ void __launch_bounds__(256)
prep_a_kernel(const float* __restrict__ w_src,
              const float* __restrict__ w_dst,
              const float* __restrict__ w1)
{
    int t = blockIdx.x * 256 + threadIdx.x;
    const float* brow;
    int k, idx;
    uint4* dst;
    if (t < 4096) {                 // proj
        int lane = t & 31, jb = (t >> 5) & 15, k16 = t >> 9;
        int g = lane >> 2, t4 = lane & 3;
        int nn = jb * 8 + g;
        k = k16 * 16 + 2 * t4;
        brow = (nn < 64) ? (w_src + (size_t)nn * 128) : (w_dst + (size_t)(nn - 64) * 128);
        dst = g_bfrag_proj; idx = t;
    } else if (t < 6144) {          // mlp1
        int u = t - 4096;
        int lane = u & 31, jb = (u >> 5) & 15, k16 = u >> 9;
        int g = lane >> 2, t4 = lane & 3;
        int nn = jb * 8 + g;
        k = k16 * 16 + 2 * t4;
        brow = w1 + (size_t)nn * 64;
        dst = g_bfrag_mlp1; idx = u;
    } else return;

    float v0 = brow[k], v1 = brow[k + 1], v8 = brow[k + 8], v9 = brow[k + 9];
    unsigned l0, l1;
    unsigned h0 = pack_split_hi(v0, v1, l0);
    unsigned h1 = pack_split_hi(v8, v9, l1);
    dst[idx] = make_uint4(h0, h1, l0, l1);
}

// =====================================================================
// Kernel P-b: prepack B fragments for edge + mlp2.
// =====================================================================
__global__ void __launch_bounds__(256)
prep_b_kernel(const float* __restrict__ w_edge,
              const float* __restrict__ w2)
{
    int t = blockIdx.x * 256 + threadIdx.x;
    const float* brow;
    int k, idx;
    uint4* dst;
    if (t < 2048) {                 // mlp2
        int lane = t & 31, jb = (t >> 5) & 7, k16 = t >> 8;
        int g = lane >> 2, t4 = lane & 3;
        int nn = jb * 8 + g;
        k = k16 * 16 + 2 * t4;
        brow = w2 + (size_t)nn * 128;
        dst = g_bfrag_mlp2; idx = t;
    } else if (t < 2560) {          // edge
        int u = t - 2048;
        int lane = u & 31, j = (u >> 5) & 7, ks = u >> 8;
        int g = lane >> 2, t4 = lane & 3;
        int nn = j * 8 + g;
        k = ks * 16 + 2 * t4;
        brow = w_edge + (size_t)nn * 32;
        dst = g_bfrag_edge; idx = u;
    } else return;

    float v0 = brow[k], v1 = brow[k + 1], v8 = brow[k + 8], v9 = brow[k + 9];
    unsigned l0, l1;
    unsigned h0 = pack_split_hi(v0, v1, l0);
    unsigned h1 = pack_split_hi(v8, v9, l1);
    dst[idx] = make_uint4(h0, h1, l0, l1);
}

// =====================================================================
// Kernel A: proj via tensor MMA. tile 128 nodes x 128 ch, 8 warps (4 rb x 2 cb).
// cb=0 -> g_src channels, cb=1 -> g_dst channels.
// =====================================================================
__global__ void __launch_bounds__(256)
proj_kernel(const float* __restrict__ x, int n)
{
    __shared__ __align__(16) __nv_bfloat16 ash[128][40];
    __shared__ __align__(16) __nv_bfloat16 asl[128][40];
    const int tid = threadIdx.x;
    const int warp = tid >> 5, lane = tid & 31;
    const int rb = warp >> 1, cb = warp & 1;
    const int g = lane >> 2, t4 = lane & 3;
    const int n0 = blockIdx.x * 128;

    float acc[2][8][4];
#pragma unroll
    for (int mf = 0; mf < 2; mf++)
#pragma unroll
        for (int j = 0; j < 8; j++)
#pragma unroll
            for (int q = 0; q < 4; q++) acc[mf][j][q] = 0.f;

    for (int dt = 0; dt < 128; dt += 32) {
#pragma unroll
        for (int it = 0; it < 4; it++) {
            int i = tid + it * 256;
            int row = i >> 3, q = i & 7;
            int gn = n0 + row;
            float4 v = make_float4(0.f, 0.f, 0.f, 0.f);
            if (gn < n) v = *(const float4*)&x[(size_t)gn * 128 + dt + q * 4];
            unsigned l0, l1;
            unsigned h0 = pack_split_hi(v.x, v.y, l0);
            unsigned h1 = pack_split_hi(v.z, v.w, l1);
            *(uint2*)&ash[row][q * 4] = make_uint2(h0, h1);
            *(uint2*)&asl[row][q * 4] = make_uint2(l0, l1);
        }
        __syncthreads();

#pragma unroll
        for (int ks = 0; ks < 2; ks++) {
            int k16 = (dt >> 4) + ks;
            int c0 = ks * 16 + 2 * t4;
            unsigned ah[2][4], al[2][4];
#pragma unroll
            for (int mf = 0; mf < 2; mf++) {
                int r0 = rb * 32 + mf * 16 + g;
                ah[mf][0] = *(const unsigned*)&ash[r0][c0];
                ah[mf][1] = *(const unsigned*)&ash[r0 + 8][c0];
                ah[mf][2] = *(const unsigned*)&ash[r0][c0 + 8];
                ah[mf][3] = *(const unsigned*)&ash[r0 + 8][c0 + 8];
                al[mf][0] = *(const unsigned*)&asl[r0][c0];
                al[mf][1] = *(const unsigned*)&asl[r0 + 8][c0];
                al[mf][2] = *(const unsigned*)&asl[r0][c0 + 8];
                al[mf][3] = *(const unsigned*)&asl[r0 + 8][c0 + 8];
            }
#pragma unroll
            for (int j = 0; j < 8; j++) {
                uint4 B = g_bfrag_proj[(size_t)(k16 * 16 + cb * 8 + j) * 32 + lane];
#pragma unroll
                for (int mf = 0; mf < 2; mf++) {
                    float* d = acc[mf][j];
                    mma_bf16(d[0], d[1], d[2], d[3], ah[mf][0], ah[mf][1], ah[mf][2], ah[mf][3], B.x, B.y);
                    mma_bf16(d[0], d[1], d[2], d[3], al[mf][0], al[mf][1], al[mf][2], al[mf][3], B.x, B.y);
                    mma_bf16(d[0], d[1], d[2], d[3], ah[mf][0], ah[mf][1], ah[mf][2], ah[mf][3], B.z, B.w);
                }
            }
        }
        __syncthreads();
    }

    float* obase = cb ? g_dst : g_src;
#pragma unroll
    for (int mf = 0; mf < 2; mf++) {
        int r = n0 + rb * 32 + mf * 16 + g;
#pragma unroll
        for (int j = 0; j < 8; j++) {
            int c = j * 8 + 2 * t4;
            float* d = acc[mf][j];
            if (r < n)     *(float2*)&obase[(size_t)r * H + c]       = make_float2(d[0], d[1]);
            if (r + 8 < n) *(float2*)&obase[(size_t)(r + 8) * H + c] = make_float2(d[2], d[3]);
        }
    }
}

// =====================================================================
// Kernel B: edge MLP (tensor MMA) + max-free streaming softmax.
// 4 nodes/block, 256 thr; __launch_bounds__(256,6) -> 42 regs, 6 blocks/SM
// (smem 35.9KB x 6 = 215KB <= 227KB).
// =====================================================================
__global__ void __launch_bounds__(256, 6)
edge_kernel(const float* __restrict__ ea,
            const int*   __restrict__ ei,
            const int*   __restrict__ nbr,
            int n)
{
    __shared__ union {
        struct { __nv_bfloat16 eah[128][40]; __nv_bfloat16 eal[128][40]; } a;
        float msg[128][68];
    } su;
    __shared__ int      se_[4][KNB];
    __shared__ int      ss_[4][KNB];
    __shared__ unsigned smask[4];

    const int tid   = threadIdx.x;
    const int node0 = blockIdx.x * 4;

    if (tid < 128) {
        int local = tid >> 5, k = tid & 31;
        int node = node0 + local;
        int e = (node < n) ? nbr[(size_t)node * KNB + k] : -1;
        se_[local][k] = e;
        ss_[local][k] = (e >= 0) ? ei[e] : 0;
        unsigned msk = __ballot_sync(0xffffffffu, e >= 0);
        if (k == 0) smask[local] = msk;
    }
    __syncthreads();

#pragma unroll
    for (int it = 0; it < 4; it++) {
        int i = tid + it * 256;
        int row = i >> 3, q = i & 7;
        int local = row >> 5, k = row & 31;
        float4 v = make_float4(0.f, 0.f, 0.f, 0.f);
        if ((smask[local] >> k) & 1)
            v = *(const float4*)&ea[(size_t)se_[local][k] * EDGED + q * 4];
        unsigned l0, l1;
        unsigned h0 = pack_split_hi(v.x, v.y, l0);
        unsigned h1 = pack_split_hi(v.z, v.w, l1);
        *(uint2*)&su.a.eah[row][q * 4] = make_uint2(h0, h1);
        *(uint2*)&su.a.eal[row][q * 4] = make_uint2(l0, l1);
    }
    __syncthreads();

    const int w8 = tid >> 5, lane = tid & 31;
    const int g = lane >> 2, t4 = lane & 3;
    unsigned ah[2][4], al[2][4];
    {
        const int r0 = w8 * 16 + g, r1 = r0 + 8;
#pragma unroll
        for (int ks = 0; ks < 2; ks++) {
            int c0 = ks * 16 + 2 * t4;
            ah[ks][0] = *(const unsigned*)&su.a.eah[r0][c0];
            ah[ks][1] = *(const unsigned*)&su.a.eah[r1][c0];
            ah[ks][2] = *(const unsigned*)&su.a.eah[r0][c0 + 8];
            ah[ks][3] = *(const unsigned*)&su.a.eah[r1][c0 + 8];
            al[ks][0] = *(const unsigned*)&su.a.eal[r0][c0];
            al[ks][1] = *(const unsigned*)&su.a.eal[r1][c0];
            al[ks][2] = *(const unsigned*)&su.a.eal[r0][c0 + 8];
            al[ks][3] = *(const unsigned*)&su.a.eal[r1][c0 + 8];
        }
    }
    __syncthreads();

    {
        const int r0 = w8 * 16 + g, r1 = r0 + 8;
#pragma unroll
        for (int j = 0; j < 8; j++) {
            float d0 = 0.f, d1 = 0.f, d2 = 0.f, d3 = 0.f;
#pragma unroll
            for (int ks = 0; ks < 2; ks++) {
                uint4 B = g_bfrag_edge[(size_t)(ks * 8 + j) * 32 + lane];
                mma_bf16(d0, d1, d2, d3, ah[ks][0], ah[ks][1], ah[ks][2], ah[ks][3], B.x, B.y);
                mma_bf16(d0, d1, d2, d3, al[ks][0], al[ks][1], al[ks][2], al[ks][3], B.x, B.y);
                mma_bf16(d0, d1, d2, d3, ah[ks][0], ah[ks][1], ah[ks][2], ah[ks][3], B.z, B.w);
            }
            int c = j * 8 + 2 * t4;
            *(float2*)&su.msg[r0][c] = make_float2(d0, d1);
            *(float2*)&su.msg[r1][c] = make_float2(d2, d3);
        }
    }
    __syncthreads();

    // max-free streaming softmax: thread = (local node, channel h)
    {
        const int local = tid >> 6;
        const int h     = tid & 63;
        const int node  = node0 + local;
        const unsigned vm = smask[local];

        float den = 1e-16f, num = 0.f;
#pragma unroll
        for (int k = 0; k < KNB; k++) {
            bool valid = (vm >> k) & 1;
            float p  = su.msg[local * 32 + k][h];
            float xj = 0.f;
            if (valid)
                xj = g_src[(size_t)ss_[local][k] * H + h];
            float mm = fmaxf(p + xj, 0.f) + 1e-7f;
            float a = valid ? __expf(mm) : 0.f;
            den += a;
            num = fmaf(mm, a, num);
        }

        if (node < n) {
            float dstf = g_dst[(size_t)node * H + h];
            g_out[(size_t)node * H + h] = num / den + dstf;
        }
    }
}

// =====================================================================
// Kernel C: g_h = g_out @ w1.T via tensor MMA + fused BN partial stats.
// =====================================================================
__global__ void __launch_bounds__(256)
mlp1_kernel(int n)
{
    __shared__ __align__(16) __nv_bfloat16 ash[128][72];
    __shared__ __align__(16) __nv_bfloat16 asl[128][72];
    __shared__ float rs [4][128];
    __shared__ float rs2[4][128];
    const int tid = threadIdx.x;
    const int warp = tid >> 5, lane = tid & 31;
    const int rb = warp >> 1, cb = warp & 1;
    const int g = lane >> 2, t4 = lane & 3;
    const int n0 = blockIdx.x * 128;

#pragma unroll
    for (int it = 0; it < 8; it++) {
        int i = tid + it * 256;
        int row = i >> 4, q = i & 15;
        int gn = n0 + row;
        float4 v = make_float4(0.f, 0.f, 0.f, 0.f);
        if (gn < n) v = *(const float4*)&g_out[(size_t)gn * H + q * 4];
        unsigned l0, l1;
        unsigned h0 = pack_split_hi(v.x, v.y, l0);
        unsigned h1 = pack_split_hi(v.z, v.w, l1);
        *(uint2*)&ash[row][q * 4] = make_uint2(h0, h1);
        *(uint2*)&asl[row][q * 4] = make_uint2(l0, l1);
    }
    __syncthreads();

    float acc[2][8][4];
#pragma unroll
    for (int mf = 0; mf < 2; mf++)
#pragma unroll
        for (int j = 0; j < 8; j++)
#pragma unroll
            for (int q = 0; q < 4; q++) acc[mf][j][q] = 0.f;

#pragma unroll
    for (int k16 = 0; k16 < 4; k16++) {
        int c0 = k16 * 16 + 2 * t4;
        unsigned ah[2][4], al[2][4];
#pragma unroll
        for (int mf = 0; mf < 2; mf++) {
            int r0 = rb * 32 + mf * 16 + g;
            ah[mf][0] = *(const unsigned*)&ash[r0][c0];
            ah[mf][1] = *(const unsigned*)&ash[r0 + 8][c0];
            ah[mf][2] = *(const unsigned*)&ash[r0][c0 + 8];
            ah[mf][3] = *(const unsigned*)&ash[r0 + 8][c0 + 8];
            al[mf][0] = *(const unsigned*)&asl[r0][c0];
            al[mf][1] = *(const unsigned*)&asl[r0 + 8][c0];
            al[mf][2] = *(const unsigned*)&asl[r0][c0 + 8];
            al[mf][3] = *(const unsigned*)&asl[r0 + 8][c0 + 8];
        }
#pragma unroll
        for (int j = 0; j < 8; j++) {
            uint4 B = g_bfrag_mlp1[(size_t)(k16 * 16 + cb * 8 + j) * 32 + lane];
#pragma unroll
            for (int mf = 0; mf < 2; mf++) {
                float* d = acc[mf][j];
                mma_bf16(d[0], d[1], d[2], d[3], ah[mf][0], ah[mf][1], ah[mf][2], ah[mf][3], B.x, B.y);
                mma_bf16(d[0], d[1], d[2], d[3], al[mf][0], al[mf][1], al[mf][2], al[mf][3], B.x, B.y);
                mma_bf16(d[0], d[1], d[2], d[3], ah[mf][0], ah[mf][1], ah[mf][2], ah[mf][3], B.z, B.w);
            }
        }
    }

#pragma unroll
    for (int mf = 0; mf < 2; mf++) {
        int r = n0 + rb * 32 + mf * 16 + g;
#pragma unroll
        for (int j = 0; j < 8; j++) {
            int c = cb * 64 + j * 8 + 2 * t4;
            float* d = acc[mf][j];
            if (r < n)     *(float2*)&g_h[(size_t)r * H2 + c]       = make_float2(d[0], d[1]);
            if (r + 8 < n) *(float2*)&g_h[(size_t)(r + 8) * H2 + c] = make_float2(d[2], d[3]);
        }
    }

#pragma unroll
    for (int j = 0; j < 8; j++) {
        float s0 = 0.f, s1 = 0.f, q0 = 0.f, q1 = 0.f;
#pragma unroll
        for (int mf = 0; mf < 2; mf++) {
            float* d = acc[mf][j];
            s0 += d[0] + d[2];
            s1 += d[1] + d[3];
            q0 += d[0] * d[0] + d[2] * d[2];
            q1 += d[1] * d[1] + d[3] * d[3];
        }
#pragma unroll
        for (int off = 4; off < 32; off <<= 1) {
            s0 += __shfl_xor_sync(0xffffffffu, s0, off);
            s1 += __shfl_xor_sync(0xffffffffu, s1, off);
            q0 += __shfl_xor_sync(0xffffffffu, q0, off);
            q1 += __shfl_xor_sync(0xffffffffu, q1, off);
        }
        if (g == 0) {
            int c = cb * 64 + j * 8 + 2 * t4;
            rs [rb][c]     = s0;
            rs [rb][c + 1] = s1;
            rs2[rb][c]     = q0;
            rs2[rb][c + 1] = q1;
        }
    }
    __syncthreads();
    if (tid < 128) {
        float s  = rs [0][tid] + rs [1][tid] + rs [2][tid] + rs [3][tid];
        float s2 = rs2[0][tid] + rs2[1][tid] + rs2[2][tid] + rs2[3][tid];
        g_part[(size_t)blockIdx.x * H2 + tid]                      = s;
        g_part[(size_t)NBMAX * H2 + (size_t)blockIdx.x * H2 + tid] = s2;
    }
}

// =====================================================================
// Kernel D: single-kernel BN fold. grid = 128, 512 threads, deterministic.
// =====================================================================
__global__ void __launch_bounds__(512)
fold_kernel(const float* __restrict__ gamma, const float* __restrict__ beta,
            int n, int nb)
{
    __shared__ float sh[512], sh2[512];
    const int c = blockIdx.x;
    const int t = threadIdx.x;
    float s = 0.f, s2 = 0.f;
    if (t < nb) {
        s  = g_part[(size_t)t * H2 + c];
        s2 = g_part[(size_t)NBMAX * H2 + (size_t)t * H2 + c];
    }
    sh[t] = s; sh2[t] = s2;
    __syncthreads();
#pragma unroll
    for (int off = 256; off > 0; off >>= 1) {
        if (t < off) { sh[t] += sh[t + off]; sh2[t] += sh2[t + off]; }
        __syncthreads();
    }
    if (t == 0) {
        float inv_n = 1.f / (float)n;
        float mean  = sh[0] * inv_n;
        float var   = sh2[0] * inv_n - mean * mean;
        float sc    = gamma[c] * rsqrtf(var + 1e-5f);
        g_sb[c]      = sc;
        g_sb[H2 + c] = beta[c] - mean * sc;
    }
}

// =====================================================================
// Kernel E: out = relu(bn(g_h)) @ w2.T via tensor MMA. tile 128 x 64.
// =====================================================================
__global__ void __launch_bounds__(256)
mlp2_kernel(float* __restrict__ outp, int n)
{
    __shared__ __align__(16) __nv_bfloat16 ash[128][40];
    __shared__ __align__(16) __nv_bfloat16 asl[128][40];
    const int tid = threadIdx.x;
    const int warp = tid >> 5, lane = tid & 31;
    const int rb = warp >> 1, cb = warp & 1;
    const int g = lane >> 2, t4 = lane & 3;
    const int n0 = blockIdx.x * 128;

    float acc[2][4][4];
#pragma unroll
    for (int mf = 0; mf < 2; mf++)
#pragma unroll
        for (int j = 0; j < 4; j++)
#pragma unroll
            for (int q = 0; q < 4; q++) acc[mf][j][q] = 0.f;

    for (int dt = 0; dt < 128; dt += 32) {
#pragma unroll
        for (int it = 0; it < 4; it++) {
            int i = tid + it * 256;
            int row = i >> 3, q = i & 7;
            int gn = n0 + row;
            int d  = dt + q * 4;
            float4 v = make_float4(0.f, 0.f, 0.f, 0.f);
            if (gn < n) v = *(const float4*)&g_h[(size_t)gn * H2 + d];
            float4 sc = *(const float4*)&g_sb[d];
            float4 bi = *(const float4*)&g_sb[H2 + d];
            float r0 = fmaxf(fmaf(v.x, sc.x, bi.x), 0.f);
            float r1 = fmaxf(fmaf(v.y, sc.y, bi.y), 0.f);
            float r2 = fmaxf(fmaf(v.z, sc.z, bi.z), 0.f);
            float r3 = fmaxf(fmaf(v.w, sc.w, bi.w), 0.f);
            unsigned l0, l1;
            unsigned h0 = pack_split_hi(r0, r1, l0);
            unsigned h1 = pack_split_hi(r2, r3, l1);
            *(uint2*)&ash[row][q * 4] = make_uint2(h0, h1);
            *(uint2*)&asl[row][q * 4] = make_uint2(l0, l1);
        }
        __syncthreads();

#pragma unroll
        for (int ks = 0; ks < 2; ks++) {
            int k16 = (dt >> 4) + ks;
            int c0 = ks * 16 + 2 * t4;
            unsigned ah[2][4], al[2][4];
#pragma unroll
            for (int mf = 0; mf < 2; mf++) {
                int r0 = rb * 32 + mf * 16 + g;
                ah[mf][0] = *(const unsigned*)&ash[r0][c0];
                ah[mf][1] = *(const unsigned*)&ash[r0 + 8][c0];
                ah[mf][2] = *(const unsigned*)&ash[r0][c0 + 8];
                ah[mf][3] = *(const unsigned*)&ash[r0 + 8][c0 + 8];
                al[mf][0] = *(const unsigned*)&asl[r0][c0];
                al[mf][1] = *(const unsigned*)&asl[r0 + 8][c0];
                al[mf][2] = *(const unsigned*)&asl[r0][c0 + 8];
                al[mf][3] = *(const unsigned*)&asl[r0 + 8][c0 + 8];
            }
#pragma unroll
            for (int j = 0; j < 4; j++) {
                uint4 B = g_bfrag_mlp2[(size_t)(k16 * 8 + cb * 4 + j) * 32 + lane];
#pragma unroll
                for (int mf = 0; mf < 2; mf++) {
                    float* d = acc[mf][j];
                    mma_bf16(d[0], d[1], d[2], d[3], ah[mf][0], ah[mf][1], ah[mf][2], ah[mf][3], B.x, B.y);
                    mma_bf16(d[0], d[1], d[2], d[3], al[mf][0], al[mf][1], al[mf][2], al[mf][3], B.x, B.y);
                    mma_bf16(d[0], d[1], d[2], d[3], ah[mf][0], ah[mf][1], ah[mf][2], ah[mf][3], B.z, B.w);
                }
            }
        }
        __syncthreads();
    }

#pragma unroll
    for (int mf = 0; mf < 2; mf++) {
        int r = n0 + rb * 32 + mf * 16 + g;
#pragma unroll
        for (int j = 0; j < 4; j++) {
            int c = cb * 32 + j * 8 + 2 * t4;
            float* d = acc[mf][j];
            if (r < n)     *(float2*)&outp[(size_t)r * H + c]       = make_float2(d[0], d[1]);
            if (r + 8 < n) *(float2*)&outp[(size_t)(r + 8) * H + c] = make_float2(d[2], d[3]);
        }
    }
}

// =====================================================================
extern "C" void kernel_launch(void* const* d_in, const int* in_sizes, int n_in,
                              void* d_out, int out_size)
{
    const float* x      = (const float*)d_in[0];
    const float* ea     = (const float*)d_in[1];
    const float* w_src  = (const float*)d_in[2];
    const float* w_dst  = (const float*)d_in[3];
    const float* w_edge = (const float*)d_in[4];
    const float* w1     = (const float*)d_in[5];
    const float* gamma  = (const float*)d_in[6];
    const float* beta   = (const float*)d_in[7];
    const float* w2     = (const float*)d_in[8];
    const int*   ei     = (const int*)d_in[9];
    const int*   nbr    = (const int*)d_in[10];
    float* outp = (float*)d_out;

    int n = in_sizes[0] / INC;
    if (n > MAXN) n = MAXN;

    int gb128 = (n + 127) / 128;
    prep_a_kernel<<<24, 256>>>(w_src, w_dst, w1);        // launch 1
    proj_kernel  <<<gb128, 256>>>(x, n);                 // launch 2
    prep_b_kernel<<<10, 256>>>(w_edge, w2);              // launch 3
    edge_kernel  <<<(n + 3) / 4, 256>>>(ea, ei, nbr, n); // launch 4 (profiled)
    mlp1_kernel  <<<gb128, 256>>>(n);                    // launch 5
    fold_kernel  <<<128, 512>>>(gamma, beta, n, gb128);  // launch 6
    mlp2_kernel  <<<gb128, 256>>>(outp, n);              // launch 7
}

// round 14
// speedup vs baseline: 1.0528x; 1.0528x over previous
#include <cuda_runtime.h>
#include <cuda_bf16.h>
#include <cstdint>

#define MAXN   50000
#define KNB    32
#define INC    128
#define H      64
#define EDGED  32
#define H2     128
#define NBMAX  391   // ceil(MAXN/128)

// ---------------- scratch (static device memory; no allocation) ----------------
__device__ float g_src [(size_t)MAXN * H];    // x @ w_src.T
__device__ float g_dst [(size_t)MAXN * H];    // x @ w_dst.T
__device__ float g_out [(size_t)MAXN * H];
__device__ float g_h   [(size_t)MAXN * H2];
__device__ float g_part [2 * NBMAX * H2];
__device__ float g_sb  [2 * H2];

// Prepacked B fragments (bf16 hi/lo split, MMA register layout):
// uint4 = {bh0, bh1, bl0, bl1} per lane.
__device__ uint4 g_bfrag_proj[8 * 16 * 32];   // [k16][jb(16)][lane]
__device__ uint4 g_bfrag_mlp2[8 * 8 * 32];    // [k16][jb(8)][lane]
__device__ uint4 g_bfrag_edge[2 * 8 * 32];    // [ks][j(8)][lane]
__device__ uint4 g_bfrag_mlp1[4 * 16 * 32];   // [k16][jb(16)][lane]

// ---------------- helpers ----------------
// bf16 hi/lo split using the packed cvt: 6 instrs/pair, same rn rounding
// as __float2bfloat16 (bit-identical results, ~40% fewer ALU ops).
__device__ __forceinline__ unsigned pack_split_hi(float a, float b,
                                                  unsigned& lo_pack) {
    unsigned hi;
    asm("cvt.rn.bf16x2.f32 %0, %1, %2;" : "=r"(hi) : "f"(b), "f"(a));
    float ah = __uint_as_float(hi << 16);
    float bh = __uint_as_float(hi & 0xffff0000u);
    float ra = a - ah;
    float rb = b - bh;
    unsigned lo;
    asm("cvt.rn.bf16x2.f32 %0, %1, %2;" : "=r"(lo) : "f"(rb), "f"(ra));
    lo_pack = lo;
    return hi;
}

__device__ __forceinline__ void mma_bf16(float& d0, float& d1, float& d2, float& d3,
                                         unsigned a0, unsigned a1, unsigned a2, unsigned a3,
                                         unsigned b0, unsigned b1) {
    asm volatile(
        "mma.sync.aligned.m16n8k16.row.col.f32.bf16.bf16.f32 "
        "{%0,%1,%2,%3}, {%4,%5,%6,%7}, {%8,%9}, {%0,%1,%2,%3};"
        : "+f"(d0), "+f"(d1), "+f"(d2), "+f"(d3)
        : "r"(a0), "r"(a1), "r"(a2), "r"(a3), "r"(b0), "r"(b1));
}

// =====================================================================
// Kernel P-a: prepack B fragments for proj + mlp1.
// =====================================================================
__global__ void __launch_bounds__(256)
prep_a_kernel(const float* __restrict__ w_src,
              const float* __restrict__ w_dst,
              const float* __restrict__ w1)
{
    int t = blockIdx.x * 256 + threadIdx.x;
    const float* brow;
    int k, idx;
    uint4* dst;
    if (t < 4096) {                 // proj
        int lane = t & 31, jb = (t >> 5) & 15, k16 = t >> 9;
        int g = lane >> 2, t4 = lane & 3;
        int nn = jb * 8 + g;
        k = k16 * 16 + 2 * t4;
        brow = (nn < 64) ? (w_src + (size_t)nn * 128) : (w_dst + (size_t)(nn - 64) * 128);
        dst = g_bfrag_proj; idx = t;
    } else if (t < 6144) {          // mlp1
        int u = t - 4096;
        int lane = u & 31, jb = (u >> 5) & 15, k16 = u >> 9;
        int g = lane >> 2, t4 = lane & 3;
        int nn = jb * 8 + g;
        k = k16 * 16 + 2 * t4;
        brow = w1 + (size_t)nn * 64;
        dst = g_bfrag_mlp1; idx = u;
    } else return;

    float v0 = brow[k], v1 = brow[k + 1], v8 = brow[k + 8], v9 = brow[k + 9];
    unsigned l0, l1;
    unsigned h0 = pack_split_hi(v0, v1, l0);
    unsigned h1 = pack_split_hi(v8, v9, l1);
    dst[idx] = make_uint4(h0, h1, l0, l1);
}

// =====================================================================
// Kernel P-b: prepack B fragments for edge + mlp2.
// =====================================================================
__global__ void __launch_bounds__(256)
prep_b_kernel(const float* __restrict__ w_edge,
              const float* __restrict__ w2)
{
    int t = blockIdx.x * 256 + threadIdx.x;
    const float* brow;
    int k, idx;
    uint4* dst;
    if (t < 2048) {                 // mlp2
        int lane = t & 31, jb = (t >> 5) & 7, k16 = t >> 8;
        int g = lane >> 2, t4 = lane & 3;
        int nn = jb * 8 + g;
        k = k16 * 16 + 2 * t4;
        brow = w2 + (size_t)nn * 128;
        dst = g_bfrag_mlp2; idx = t;
    } else if (t < 2560) {          // edge
        int u = t - 2048;
        int lane = u & 31, j = (u >> 5) & 7, ks = u >> 8;
        int g = lane >> 2, t4 = lane & 3;
        int nn = j * 8 + g;
        k = ks * 16 + 2 * t4;
        brow = w_edge + (size_t)nn * 32;
        dst = g_bfrag_edge; idx = u;
    } else return;

    float v0 = brow[k], v1 = brow[k + 1], v8 = brow[k + 8], v9 = brow[k + 9];
    unsigned l0, l1;
    unsigned h0 = pack_split_hi(v0, v1, l0);
    unsigned h1 = pack_split_hi(v8, v9, l1);
    dst[idx] = make_uint4(h0, h1, l0, l1);
}

// =====================================================================
// Kernel A: proj via tensor MMA. tile 128 nodes x 128 ch, 8 warps (4 rb x 2 cb).
// cb=0 -> g_src channels, cb=1 -> g_dst channels.
// =====================================================================
__global__ void __launch_bounds__(256)
proj_kernel(const float* __restrict__ x, int n)
{
    __shared__ __align__(16) __nv_bfloat16 ash[128][40];
    __shared__ __align__(16) __nv_bfloat16 asl[128][40];
    const int tid = threadIdx.x;
    const int warp = tid >> 5, lane = tid & 31;
    const int rb = warp >> 1, cb = warp & 1;
    const int g = lane >> 2, t4 = lane & 3;
    const int n0 = blockIdx.x * 128;

    float acc[2][8][4];
#pragma unroll
    for (int mf = 0; mf < 2; mf++)
#pragma unroll
        for (int j = 0; j < 8; j++)
#pragma unroll
            for (int q = 0; q < 4; q++) acc[mf][j][q] = 0.f;

    for (int dt = 0; dt < 128; dt += 32) {
#pragma unroll
        for (int it = 0; it < 4; it++) {
            int i = tid + it * 256;
            int row = i >> 3, q = i & 7;
            int gn = n0 + row;
            float4 v = make_float4(0.f, 0.f, 0.f, 0.f);
            if (gn < n) v = *(const float4*)&x[(size_t)gn * 128 + dt + q * 4];
            unsigned l0, l1;
            unsigned h0 = pack_split_hi(v.x, v.y, l0);
            unsigned h1 = pack_split_hi(v.z, v.w, l1);
            *(uint2*)&ash[row][q * 4] = make_uint2(h0, h1);
            *(uint2*)&asl[row][q * 4] = make_uint2(l0, l1);
        }
        __syncthreads();

#pragma unroll
        for (int ks = 0; ks < 2; ks++) {
            int k16 = (dt >> 4) + ks;
            int c0 = ks * 16 + 2 * t4;
            unsigned ah[2][4], al[2][4];
#pragma unroll
            for (int mf = 0; mf < 2; mf++) {
                int r0 = rb * 32 + mf * 16 + g;
                ah[mf][0] = *(const unsigned*)&ash[r0][c0];
                ah[mf][1] = *(const unsigned*)&ash[r0 + 8][c0];
                ah[mf][2] = *(const unsigned*)&ash[r0][c0 + 8];
                ah[mf][3] = *(const unsigned*)&ash[r0 + 8][c0 + 8];
                al[mf][0] = *(const unsigned*)&asl[r0][c0];
                al[mf][1] = *(const unsigned*)&asl[r0 + 8][c0];
                al[mf][2] = *(const unsigned*)&asl[r0][c0 + 8];
                al[mf][3] = *(const unsigned*)&asl[r0 + 8][c0 + 8];
            }
#pragma unroll
            for (int j = 0; j < 8; j++) {
                uint4 B = g_bfrag_proj[(size_t)(k16 * 16 + cb * 8 + j) * 32 + lane];
#pragma unroll
                for (int mf = 0; mf < 2; mf++) {
                    float* d = acc[mf][j];
                    mma_bf16(d[0], d[1], d[2], d[3], ah[mf][0], ah[mf][1], ah[mf][2], ah[mf][3], B.x, B.y);
                    mma_bf16(d[0], d[1], d[2], d[3], al[mf][0], al[mf][1], al[mf][2], al[mf][3], B.x, B.y);
                    mma_bf16(d[0], d[1], d[2], d[3], ah[mf][0], ah[mf][1], ah[mf][2], ah[mf][3], B.z, B.w);
                }
            }
        }
        __syncthreads();
    }

    float* obase = cb ? g_dst : g_src;
#pragma unroll
    for (int mf = 0; mf < 2; mf++) {
        int r = n0 + rb * 32 + mf * 16 + g;
#pragma unroll
        for (int j = 0; j < 8; j++) {
            int c = j * 8 + 2 * t4;
            float* d = acc[mf][j];
            if (r < n)     *(float2*)&obase[(size_t)r * H + c]       = make_float2(d[0], d[1]);
            if (r + 8 < n) *(float2*)&obase[(size_t)(r + 8) * H + c] = make_float2(d[2], d[3]);
        }
    }
}

// =====================================================================
// Kernel B: edge MLP (tensor MMA) + max-free streaming softmax.
// 4 nodes/block, 256 thr; __launch_bounds__(256,5) -> proven 5 blocks/SM
// sweet spot (R13's (256,6)/42-reg cap spilled: L1 63->83%, dur +12us).
// =====================================================================
__global__ void __launch_bounds__(256, 5)
edge_kernel(const float* __restrict__ ea,
            const int*   __restrict__ ei,
            const int*   __restrict__ nbr,
            int n)
{
    __shared__ union {
        struct { __nv_bfloat16 eah[128][40]; __nv_bfloat16 eal[128][40]; } a;
        float msg[128][68];
    } su;
    __shared__ int      se_[4][KNB];
    __shared__ int      ss_[4][KNB];
    __shared__ unsigned smask[4];

    const int tid   = threadIdx.x;
    const int node0 = blockIdx.x * 4;

    if (tid < 128) {
        int local = tid >> 5, k = tid & 31;
        int node = node0 + local;
        int e = (node < n) ? nbr[(size_t)node * KNB + k] : -1;
        se_[local][k] = e;
        ss_[local][k] = (e >= 0) ? ei[e] : 0;
        unsigned msk = __ballot_sync(0xffffffffu, e >= 0);
        if (k == 0) smask[local] = msk;
    }
    __syncthreads();

#pragma unroll
    for (int it = 0; it < 4; it++) {
        int i = tid + it * 256;
        int row = i >> 3, q = i & 7;
        int local = row >> 5, k = row & 31;
        float4 v = make_float4(0.f, 0.f, 0.f, 0.f);
        if ((smask[local] >> k) & 1)
            v = *(const float4*)&ea[(size_t)se_[local][k] * EDGED + q * 4];
        unsigned l0, l1;
        unsigned h0 = pack_split_hi(v.x, v.y, l0);
        unsigned h1 = pack_split_hi(v.z, v.w, l1);
        *(uint2*)&su.a.eah[row][q * 4] = make_uint2(h0, h1);
        *(uint2*)&su.a.eal[row][q * 4] = make_uint2(l0, l1);
    }
    __syncthreads();

    const int w8 = tid >> 5, lane = tid & 31;
    const int g = lane >> 2, t4 = lane & 3;
    unsigned ah[2][4], al[2][4];
    {
        const int r0 = w8 * 16 + g, r1 = r0 + 8;
#pragma unroll
        for (int ks = 0; ks < 2; ks++) {
            int c0 = ks * 16 + 2 * t4;
            ah[ks][0] = *(const unsigned*)&su.a.eah[r0][c0];
            ah[ks][1] = *(const unsigned*)&su.a.eah[r1][c0];
            ah[ks][2] = *(const unsigned*)&su.a.eah[r0][c0 + 8];
            ah[ks][3] = *(const unsigned*)&su.a.eah[r1][c0 + 8];
            al[ks][0] = *(const unsigned*)&su.a.eal[r0][c0];
            al[ks][1] = *(const unsigned*)&su.a.eal[r1][c0];
            al[ks][2] = *(const unsigned*)&su.a.eal[r0][c0 + 8];
            al[ks][3] = *(const unsigned*)&su.a.eal[r1][c0 + 8];
        }
    }
    __syncthreads();

    {
        const int r0 = w8 * 16 + g, r1 = r0 + 8;
#pragma unroll
        for (int j = 0; j < 8; j++) {
            float d0 = 0.f, d1 = 0.f, d2 = 0.f, d3 = 0.f;
#pragma unroll
            for (int ks = 0; ks < 2; ks++) {
                uint4 B = g_bfrag_edge[(size_t)(ks * 8 + j) * 32 + lane];
                mma_bf16(d0, d1, d2, d3, ah[ks][0], ah[ks][1], ah[ks][2], ah[ks][3], B.x, B.y);
                mma_bf16(d0, d1, d2, d3, al[ks][0], al[ks][1], al[ks][2], al[ks][3], B.x, B.y);
                mma_bf16(d0, d1, d2, d3, ah[ks][0], ah[ks][1], ah[ks][2], ah[ks][3], B.z, B.w);
            }
            int c = j * 8 + 2 * t4;
            *(float2*)&su.msg[r0][c] = make_float2(d0, d1);
            *(float2*)&su.msg[r1][c] = make_float2(d2, d3);
        }
    }
    __syncthreads();

    // max-free streaming softmax: thread = (local node, channel h)
    {
        const int local = tid >> 6;
        const int h     = tid & 63;
        const int node  = node0 + local;
        const unsigned vm = smask[local];

        float den = 1e-16f, num = 0.f;
#pragma unroll
        for (int k = 0; k < KNB; k++) {
            bool valid = (vm >> k) & 1;
            float p  = su.msg[local * 32 + k][h];
            float xj = 0.f;
            if (valid)
                xj = g_src[(size_t)ss_[local][k] * H + h];
            float mm = fmaxf(p + xj, 0.f) + 1e-7f;
            float a = valid ? __expf(mm) : 0.f;
            den += a;
            num = fmaf(mm, a, num);
        }

        if (node < n) {
            float dstf = g_dst[(size_t)node * H + h];
            g_out[(size_t)node * H + h] = num / den + dstf;
        }
    }
}

// =====================================================================
// Kernel C: g_h = g_out @ w1.T via tensor MMA + fused BN partial stats.
// =====================================================================
__global__ void __launch_bounds__(256)
mlp1_kernel(int n)
{
    __shared__ __align__(16) __nv_bfloat16 ash[128][72];
    __shared__ __align__(16) __nv_bfloat16 asl[128][72];
    __shared__ float rs [4][128];
    __shared__ float rs2[4][128];
    const int tid = threadIdx.x;
    const int warp = tid >> 5, lane = tid & 31;
    const int rb = warp >> 1, cb = warp & 1;
    const int g = lane >> 2, t4 = lane & 3;
    const int n0 = blockIdx.x * 128;

#pragma unroll
    for (int it = 0; it < 8; it++) {
        int i = tid + it * 256;
        int row = i >> 4, q = i & 15;
        int gn = n0 + row;
        float4 v = make_float4(0.f, 0.f, 0.f, 0.f);
        if (gn < n) v = *(const float4*)&g_out[(size_t)gn * H + q * 4];
        unsigned l0, l1;
        unsigned h0 = pack_split_hi(v.x, v.y, l0);
        unsigned h1 = pack_split_hi(v.z, v.w, l1);
        *(uint2*)&ash[row][q * 4] = make_uint2(h0, h1);
        *(uint2*)&asl[row][q * 4] = make_uint2(l0, l1);
    }
    __syncthreads();

    float acc[2][8][4];
#pragma unroll
    for (int mf = 0; mf < 2; mf++)
#pragma unroll
        for (int j = 0; j < 8; j++)
#pragma unroll
            for (int q = 0; q < 4; q++) acc[mf][j][q] = 0.f;

#pragma unroll
    for (int k16 = 0; k16 < 4; k16++) {
        int c0 = k16 * 16 + 2 * t4;
        unsigned ah[2][4], al[2][4];
#pragma unroll
        for (int mf = 0; mf < 2; mf++) {
            int r0 = rb * 32 + mf * 16 + g;
            ah[mf][0] = *(const unsigned*)&ash[r0][c0];
            ah[mf][1] = *(const unsigned*)&ash[r0 + 8][c0];
            ah[mf][2] = *(const unsigned*)&ash[r0][c0 + 8];
            ah[mf][3] = *(const unsigned*)&ash[r0 + 8][c0 + 8];
            al[mf][0] = *(const unsigned*)&asl[r0][c0];
            al[mf][1] = *(const unsigned*)&asl[r0 + 8][c0];
            al[mf][2] = *(const unsigned*)&asl[r0][c0 + 8];
            al[mf][3] = *(const unsigned*)&asl[r0 + 8][c0 + 8];
        }
#pragma unroll
        for (int j = 0; j < 8; j++) {
            uint4 B = g_bfrag_mlp1[(size_t)(k16 * 16 + cb * 8 + j) * 32 + lane];
#pragma unroll
            for (int mf = 0; mf < 2; mf++) {
                float* d = acc[mf][j];
                mma_bf16(d[0], d[1], d[2], d[3], ah[mf][0], ah[mf][1], ah[mf][2], ah[mf][3], B.x, B.y);
                mma_bf16(d[0], d[1], d[2], d[3], al[mf][0], al[mf][1], al[mf][2], al[mf][3], B.x, B.y);
                mma_bf16(d[0], d[1], d[2], d[3], ah[mf][0], ah[mf][1], ah[mf][2], ah[mf][3], B.z, B.w);
            }
        }
    }

#pragma unroll
    for (int mf = 0; mf < 2; mf++) {
        int r = n0 + rb * 32 + mf * 16 + g;
#pragma unroll
        for (int j = 0; j < 8; j++) {
            int c = cb * 64 + j * 8 + 2 * t4;
            float* d = acc[mf][j];
            if (r < n)     *(float2*)&g_h[(size_t)r * H2 + c]       = make_float2(d[0], d[1]);
            if (r + 8 < n) *(float2*)&g_h[(size_t)(r + 8) * H2 + c] = make_float2(d[2], d[3]);
        }
    }

#pragma unroll
    for (int j = 0; j < 8; j++) {
        float s0 = 0.f, s1 = 0.f, q0 = 0.f, q1 = 0.f;
#pragma unroll
        for (int mf = 0; mf < 2; mf++) {
            float* d = acc[mf][j];
            s0 += d[0] + d[2];
            s1 += d[1] + d[3];
            q0 += d[0] * d[0] + d[2] * d[2];
            q1 += d[1] * d[1] + d[3] * d[3];
        }
#pragma unroll
        for (int off = 4; off < 32; off <<= 1) {
            s0 += __shfl_xor_sync(0xffffffffu, s0, off);
            s1 += __shfl_xor_sync(0xffffffffu, s1, off);
            q0 += __shfl_xor_sync(0xffffffffu, q0, off);
            q1 += __shfl_xor_sync(0xffffffffu, q1, off);
        }
        if (g == 0) {
            int c = cb * 64 + j * 8 + 2 * t4;
            rs [rb][c]     = s0;
            rs [rb][c + 1] = s1;
            rs2[rb][c]     = q0;
            rs2[rb][c + 1] = q1;
        }
    }
    __syncthreads();
    if (tid < 128) {
        float s  = rs [0][tid] + rs [1][tid] + rs [2][tid] + rs [3][tid];
        float s2 = rs2[0][tid] + rs2[1][tid] + rs2[2][tid] + rs2[3][tid];
        g_part[(size_t)blockIdx.x * H2 + tid]                      = s;
        g_part[(size_t)NBMAX * H2 + (size_t)blockIdx.x * H2 + tid] = s2;
    }
}

// =====================================================================
// Kernel D: single-kernel BN fold. grid = 128, 512 threads, deterministic.
// =====================================================================
__global__ void __launch_bounds__(512)
fold_kernel(const float* __restrict__ gamma, const float* __restrict__ beta,
            int n, int nb)
{
    __shared__ float sh[512], sh2[512];
    const int c = blockIdx.x;
    const int t = threadIdx.x;
    float s = 0.f, s2 = 0.f;
    if (t < nb) {
        s  = g_part[(size_t)t * H2 + c];
        s2 = g_part[(size_t)NBMAX * H2 + (size_t)t * H2 + c];
    }
    sh[t] = s; sh2[t] = s2;
    __syncthreads();
#pragma unroll
    for (int off = 256; off > 0; off >>= 1) {
        if (t < off) { sh[t] += sh[t + off]; sh2[t] += sh2[t + off]; }
        __syncthreads();
    }
    if (t == 0) {
        float inv_n = 1.f / (float)n;
        float mean  = sh[0] * inv_n;
        float var   = sh2[0] * inv_n - mean * mean;
        float sc    = gamma[c] * rsqrtf(var + 1e-5f);
        g_sb[c]      = sc;
        g_sb[H2 + c] = beta[c] - mean * sc;
    }
}

// =====================================================================
// Kernel E: out = relu(bn(g_h)) @ w2.T via tensor MMA. tile 128 x 64.
// =====================================================================
__global__ void __launch_bounds__(256)
mlp2_kernel(float* __restrict__ outp, int n)
{
    __shared__ __align__(16) __nv_bfloat16 ash[128][40];
    __shared__ __align__(16) __nv_bfloat16 asl[128][40];
    const int tid = threadIdx.x;
    const int warp = tid >> 5, lane = tid & 31;
    const int rb = warp >> 1, cb = warp & 1;
    const int g = lane >> 2, t4 = lane & 3;
    const int n0 = blockIdx.x * 128;

    float acc[2][4][4];
#pragma unroll
    for (int mf = 0; mf < 2; mf++)
#pragma unroll
        for (int j = 0; j < 4; j++)
#pragma unroll
            for (int q = 0; q < 4; q++) acc[mf][j][q] = 0.f;

    for (int dt = 0; dt < 128; dt += 32) {
#pragma unroll
        for (int it = 0; it < 4; it++) {
            int i = tid + it * 256;
            int row = i >> 3, q = i & 7;
            int gn = n0 + row;
            int d  = dt + q * 4;
            float4 v = make_float4(0.f, 0.f, 0.f, 0.f);
            if (gn < n) v = *(const float4*)&g_h[(size_t)gn * H2 + d];
            float4 sc = *(const float4*)&g_sb[d];
            float4 bi = *(const float4*)&g_sb[H2 + d];
            float r0 = fmaxf(fmaf(v.x, sc.x, bi.x), 0.f);
            float r1 = fmaxf(fmaf(v.y, sc.y, bi.y), 0.f);
            float r2 = fmaxf(fmaf(v.z, sc.z, bi.z), 0.f);
            float r3 = fmaxf(fmaf(v.w, sc.w, bi.w), 0.f);
            unsigned l0, l1;
            unsigned h0 = pack_split_hi(r0, r1, l0);
            unsigned h1 = pack_split_hi(r2, r3, l1);
            *(uint2*)&ash[row][q * 4] = make_uint2(h0, h1);
            *(uint2*)&asl[row][q * 4] = make_uint2(l0, l1);
        }
        __syncthreads();

#pragma unroll
        for (int ks = 0; ks < 2; ks++) {
            int k16 = (dt >> 4) + ks;
            int c0 = ks * 16 + 2 * t4;
            unsigned ah[2][4], al[2][4];
#pragma unroll
            for (int mf = 0; mf < 2; mf++) {
                int r0 = rb * 32 + mf * 16 + g;
                ah[mf][0] = *(const unsigned*)&ash[r0][c0];
                ah[mf][1] = *(const unsigned*)&ash[r0 + 8][c0];
                ah[mf][2] = *(const unsigned*)&ash[r0][c0 + 8];
                ah[mf][3] = *(const unsigned*)&ash[r0 + 8][c0 + 8];
                al[mf][0] = *(const unsigned*)&asl[r0][c0];
                al[mf][1] = *(const unsigned*)&asl[r0 + 8][c0];
                al[mf][2] = *(const unsigned*)&asl[r0][c0 + 8];
                al[mf][3] = *(const unsigned*)&asl[r0 + 8][c0 + 8];
            }
#pragma unroll
            for (int j = 0; j < 4; j++) {
                uint4 B = g_bfrag_mlp2[(size_t)(k16 * 8 + cb * 4 + j) * 32 + lane];
#pragma unroll
                for (int mf = 0; mf < 2; mf++) {
                    float* d = acc[mf][j];
                    mma_bf16(d[0], d[1], d[2], d[3], ah[mf][0], ah[mf][1], ah[mf][2], ah[mf][3], B.x, B.y);
                    mma_bf16(d[0], d[1], d[2], d[3], al[mf][0], al[mf][1], al[mf][2], al[mf][3], B.x, B.y);
                    mma_bf16(d[0], d[1], d[2], d[3], ah[mf][0], ah[mf][1], ah[mf][2], ah[mf][3], B.z, B.w);
                }
            }
        }
        __syncthreads();
    }

#pragma unroll
    for (int mf = 0; mf < 2; mf++) {
        int r = n0 + rb * 32 + mf * 16 + g;
#pragma unroll
        for (int j = 0; j < 4; j++) {
            int c = cb * 32 + j * 8 + 2 * t4;
            float* d = acc[mf][j];
            if (r < n)     *(float2*)&outp[(size_t)r * H + c]       = make_float2(d[0], d[1]);
            if (r + 8 < n) *(float2*)&outp[(size_t)(r + 8) * H + c] = make_float2(d[2], d[3]);
        }
    }
}

// =====================================================================
extern "C" void kernel_launch(void* const* d_in, const int* in_sizes, int n_in,
                              void* d_out, int out_size)
{
    const float* x      = (const float*)d_in[0];
    const float* ea     = (const float*)d_in[1];
    const float* w_src  = (const float*)d_in[2];
    const float* w_dst  = (const float*)d_in[3];
    const float* w_edge = (const float*)d_in[4];
    const float* w1     = (const float*)d_in[5];
    const float* gamma  = (const float*)d_in[6];
    const float* beta   = (const float*)d_in[7];
    const float* w2     = (const float*)d_in[8];
    const int*   ei     = (const int*)d_in[9];
    const int*   nbr    = (const int*)d_in[10];
    float* outp = (float*)d_out;

    int n = in_sizes[0] / INC;
    if (n > MAXN) n = MAXN;

    int gb128 = (n + 127) / 128;
    prep_a_kernel<<<24, 256>>>(w_src, w_dst, w1);        // launch 1
    proj_kernel  <<<gb128, 256>>>(x, n);                 // launch 2
    prep_b_kernel<<<10, 256>>>(w_edge, w2);              // launch 3
    edge_kernel  <<<(n + 3) / 4, 256>>>(ea, ei, nbr, n); // launch 4 (profiled)
    mlp1_kernel  <<<gb128, 256>>>(n);                    // launch 5
    fold_kernel  <<<128, 512>>>(gamma, beta, n, gb128);  // launch 6
    mlp2_kernel  <<<gb128, 256>>>(outp, n);              // launch 7
}

// round 15
// speedup vs baseline: 1.1505x; 1.0928x over previous
#include <cuda_runtime.h>
#include <cuda_bf16.h>
#include <cstdint>

#define MAXN   50000
#define KNB    32
#define INC    128
#define H      64
#define EDGED  32
#define H2     128
#define NBMAX  391   // ceil(MAXN/128)

// ---------------- scratch (static device memory; no allocation) ----------------
__device__ float g_src [(size_t)MAXN * H];    // x @ w_src.T
__device__ float g_dst [(size_t)MAXN * H];    // x @ w_dst.T
__device__ float g_out [(size_t)MAXN * H];
__device__ float g_h   [(size_t)MAXN * H2];
__device__ float g_part [2 * NBMAX * H2];
__device__ float g_sb  [2 * H2];

// Prepacked B fragments (bf16 hi/lo split, MMA register layout):
// uint4 = {bh0, bh1, bl0, bl1} per lane.
__device__ uint4 g_bfrag_proj[8 * 16 * 32];   // [k16][jb(16)][lane]
__device__ uint4 g_bfrag_mlp2[8 * 8 * 32];    // [k16][jb(8)][lane]
__device__ uint4 g_bfrag_edge[2 * 8 * 32];    // [ks][j(8)][lane]
__device__ uint4 g_bfrag_mlp1[4 * 16 * 32];   // [k16][jb(16)][lane]

// ---------------- helpers ----------------
// bf16 hi/lo split using the packed cvt: 6 instrs/pair, same rn rounding
// as __float2bfloat16 (bit-identical results).
__device__ __forceinline__ unsigned pack_split_hi(float a, float b,
                                                  unsigned& lo_pack) {
    unsigned hi;
    asm("cvt.rn.bf16x2.f32 %0, %1, %2;" : "=r"(hi) : "f"(b), "f"(a));
    float ah = __uint_as_float(hi << 16);
    float bh = __uint_as_float(hi & 0xffff0000u);
    float ra = a - ah;
    float rb = b - bh;
    unsigned lo;
    asm("cvt.rn.bf16x2.f32 %0, %1, %2;" : "=r"(lo) : "f"(rb), "f"(ra));
    lo_pack = lo;
    return hi;
}

__device__ __forceinline__ void mma_bf16(float& d0, float& d1, float& d2, float& d3,
                                         unsigned a0, unsigned a1, unsigned a2, unsigned a3,
                                         unsigned b0, unsigned b1) {
    asm volatile(
        "mma.sync.aligned.m16n8k16.row.col.f32.bf16.bf16.f32 "
        "{%0,%1,%2,%3}, {%4,%5,%6,%7}, {%8,%9}, {%0,%1,%2,%3};"
        : "+f"(d0), "+f"(d1), "+f"(d2), "+f"(d3)
        : "r"(a0), "r"(a1), "r"(a2), "r"(a3), "r"(b0), "r"(b1));
}

// =====================================================================
// Kernel P-a: prepack B fragments for proj + mlp1.
// =====================================================================
__global__ void __launch_bounds__(256)
prep_a_kernel(const float* __restrict__ w_src,
              const float* __restrict__ w_dst,
              const float* __restrict__ w1)
{
    int t = blockIdx.x * 256 + threadIdx.x;
    const float* brow;
    int k, idx;
    uint4* dst;
    if (t < 4096) {                 // proj
        int lane = t & 31, jb = (t >> 5) & 15, k16 = t >> 9;
        int g = lane >> 2, t4 = lane & 3;
        int nn = jb * 8 + g;
        k = k16 * 16 + 2 * t4;
        brow = (nn < 64) ? (w_src + (size_t)nn * 128) : (w_dst + (size_t)(nn - 64) * 128);
        dst = g_bfrag_proj; idx = t;
    } else if (t < 6144) {          // mlp1
        int u = t - 4096;
        int lane = u & 31, jb = (u >> 5) & 15, k16 = u >> 9;
        int g = lane >> 2, t4 = lane & 3;
        int nn = jb * 8 + g;
        k = k16 * 16 + 2 * t4;
        brow = w1 + (size_t)nn * 64;
        dst = g_bfrag_mlp1; idx = u;
    } else return;

    float v0 = brow[k], v1 = brow[k + 1], v8 = brow[k + 8], v9 = brow[k + 9];
    unsigned l0, l1;
    unsigned h0 = pack_split_hi(v0, v1, l0);
    unsigned h1 = pack_split_hi(v8, v9, l1);
    dst[idx] = make_uint4(h0, h1, l0, l1);
}

// =====================================================================
// Kernel P-b: prepack B fragments for edge + mlp2.
// =====================================================================
__global__ void __launch_bounds__(256)
prep_b_kernel(const float* __restrict__ w_edge,
              const float* __restrict__ w2)
{
    int t = blockIdx.x * 256 + threadIdx.x;
    const float* brow;
    int k, idx;
    uint4* dst;
    if (t < 2048) {                 // mlp2
        int lane = t & 31, jb = (t >> 5) & 7, k16 = t >> 8;
        int g = lane >> 2, t4 = lane & 3;
        int nn = jb * 8 + g;
        k = k16 * 16 + 2 * t4;
        brow = w2 + (size_t)nn * 128;
        dst = g_bfrag_mlp2; idx = t;
    } else if (t < 2560) {          // edge
        int u = t - 2048;
        int lane = u & 31, j = (u >> 5) & 7, ks = u >> 8;
        int g = lane >> 2, t4 = lane & 3;
        int nn = j * 8 + g;
        k = ks * 16 + 2 * t4;
        brow = w_edge + (size_t)nn * 32;
        dst = g_bfrag_edge; idx = u;
    } else return;

    float v0 = brow[k], v1 = brow[k + 1], v8 = brow[k + 8], v9 = brow[k + 9];
    unsigned l0, l1;
    unsigned h0 = pack_split_hi(v0, v1, l0);
    unsigned h1 = pack_split_hi(v8, v9, l1);
    dst[idx] = make_uint4(h0, h1, l0, l1);
}

// =====================================================================
// Kernel A: proj via tensor MMA. tile 128 nodes x 128 ch, 8 warps (4 rb x 2 cb).
// cb=0 -> g_src channels, cb=1 -> g_dst channels.
// =====================================================================
__global__ void __launch_bounds__(256)
proj_kernel(const float* __restrict__ x, int n)
{
    __shared__ __align__(16) __nv_bfloat16 ash[128][40];
    __shared__ __align__(16) __nv_bfloat16 asl[128][40];
    const int tid = threadIdx.x;
    const int warp = tid >> 5, lane = tid & 31;
    const int rb = warp >> 1, cb = warp & 1;
    const int g = lane >> 2, t4 = lane & 3;
    const int n0 = blockIdx.x * 128;

    float acc[2][8][4];
#pragma unroll
    for (int mf = 0; mf < 2; mf++)
#pragma unroll
        for (int j = 0; j < 8; j++)
#pragma unroll
            for (int q = 0; q < 4; q++) acc[mf][j][q] = 0.f;

    for (int dt = 0; dt < 128; dt += 32) {
#pragma unroll
        for (int it = 0; it < 4; it++) {
            int i = tid + it * 256;
            int row = i >> 3, q = i & 7;
            int gn = n0 + row;
            float4 v = make_float4(0.f, 0.f, 0.f, 0.f);
            if (gn < n) v = *(const float4*)&x[(size_t)gn * 128 + dt + q * 4];
            unsigned l0, l1;
            unsigned h0 = pack_split_hi(v.x, v.y, l0);
            unsigned h1 = pack_split_hi(v.z, v.w, l1);
            *(uint2*)&ash[row][q * 4] = make_uint2(h0, h1);
            *(uint2*)&asl[row][q * 4] = make_uint2(l0, l1);
        }
        __syncthreads();

#pragma unroll
        for (int ks = 0; ks < 2; ks++) {
            int k16 = (dt >> 4) + ks;
            int c0 = ks * 16 + 2 * t4;
            unsigned ah[2][4], al[2][4];
#pragma unroll
            for (int mf = 0; mf < 2; mf++) {
                int r0 = rb * 32 + mf * 16 + g;
                ah[mf][0] = *(const unsigned*)&ash[r0][c0];
                ah[mf][1] = *(const unsigned*)&ash[r0 + 8][c0];
                ah[mf][2] = *(const unsigned*)&ash[r0][c0 + 8];
                ah[mf][3] = *(const unsigned*)&ash[r0 + 8][c0 + 8];
                al[mf][0] = *(const unsigned*)&asl[r0][c0];
                al[mf][1] = *(const unsigned*)&asl[r0 + 8][c0];
                al[mf][2] = *(const unsigned*)&asl[r0][c0 + 8];
                al[mf][3] = *(const unsigned*)&asl[r0 + 8][c0 + 8];
            }
#pragma unroll
            for (int j = 0; j < 8; j++) {
                uint4 B = g_bfrag_proj[(size_t)(k16 * 16 + cb * 8 + j) * 32 + lane];
#pragma unroll
                for (int mf = 0; mf < 2; mf++) {
                    float* d = acc[mf][j];
                    mma_bf16(d[0], d[1], d[2], d[3], ah[mf][0], ah[mf][1], ah[mf][2], ah[mf][3], B.x, B.y);
                    mma_bf16(d[0], d[1], d[2], d[3], al[mf][0], al[mf][1], al[mf][2], al[mf][3], B.x, B.y);
                    mma_bf16(d[0], d[1], d[2], d[3], ah[mf][0], ah[mf][1], ah[mf][2], ah[mf][3], B.z, B.w);
                }
            }
        }
        __syncthreads();
    }

    float* obase = cb ? g_dst : g_src;
#pragma unroll
    for (int mf = 0; mf < 2; mf++) {
        int r = n0 + rb * 32 + mf * 16 + g;
#pragma unroll
        for (int j = 0; j < 8; j++) {
            int c = j * 8 + 2 * t4;
            float* d = acc[mf][j];
            if (r < n)     *(float2*)&obase[(size_t)r * H + c]       = make_float2(d[0], d[1]);
            if (r + 8 < n) *(float2*)&obase[(size_t)(r + 8) * H + c] = make_float2(d[2], d[3]);
        }
    }
}

// =====================================================================
// Kernel B: edge MLP (tensor MMA) + max-free streaming softmax.
// 4 nodes/block, 256 thr, (256,5). R15: batched staging LDGs (MLP=4),
// 2-way softmax accumulators, prescaled gather index in ss_.
// =====================================================================
__global__ void __launch_bounds__(256, 5)
edge_kernel(const float* __restrict__ ea,
            const int*   __restrict__ ei,
            const int*   __restrict__ nbr,
            int n)
{
    __shared__ union {
        struct { __nv_bfloat16 eah[128][40]; __nv_bfloat16 eal[128][40]; } a;
        float msg[128][68];
    } su;
    __shared__ int      se_[4][KNB];
    __shared__ int      ss_[4][KNB];   // holds ei[e]*H (prescaled element offset)
    __shared__ unsigned smask[4];

    const int tid   = threadIdx.x;
    const int node0 = blockIdx.x * 4;

    if (tid < 128) {
        int local = tid >> 5, k = tid & 31;
        int node = node0 + local;
        int e = (node < n) ? nbr[(size_t)node * KNB + k] : -1;
        se_[local][k] = e;
        ss_[local][k] = (e >= 0) ? (ei[e] * H) : 0;
        unsigned msk = __ballot_sync(0xffffffffu, e >= 0);
        if (k == 0) smask[local] = msk;
    }
    __syncthreads();

    // batched staging: all 4 gather loads in flight, then convert+store
    {
        float4 v[4];
#pragma unroll
        for (int it = 0; it < 4; it++) {
            int i = tid + it * 256;
            int row = i >> 3, q = i & 7;
            int local = row >> 5, k = row & 31;
            v[it] = make_float4(0.f, 0.f, 0.f, 0.f);
            if ((smask[local] >> k) & 1)
                v[it] = *(const float4*)&ea[(size_t)se_[local][k] * EDGED + q * 4];
        }
#pragma unroll
        for (int it = 0; it < 4; it++) {
            int i = tid + it * 256;
            int row = i >> 3, q = i & 7;
            unsigned l0, l1;
            unsigned h0 = pack_split_hi(v[it].x, v[it].y, l0);
            unsigned h1 = pack_split_hi(v[it].z, v[it].w, l1);
            *(uint2*)&su.a.eah[row][q * 4] = make_uint2(h0, h1);
            *(uint2*)&su.a.eal[row][q * 4] = make_uint2(l0, l1);
        }
    }
    __syncthreads();

    const int w8 = tid >> 5, lane = tid & 31;
    const int g = lane >> 2, t4 = lane & 3;
    unsigned ah[2][4], al[2][4];
    {
        const int r0 = w8 * 16 + g, r1 = r0 + 8;
#pragma unroll
        for (int ks = 0; ks < 2; ks++) {
            int c0 = ks * 16 + 2 * t4;
            ah[ks][0] = *(const unsigned*)&su.a.eah[r0][c0];
            ah[ks][1] = *(const unsigned*)&su.a.eah[r1][c0];
            ah[ks][2] = *(const unsigned*)&su.a.eah[r0][c0 + 8];
            ah[ks][3] = *(const unsigned*)&su.a.eah[r1][c0 + 8];
            al[ks][0] = *(const unsigned*)&su.a.eal[r0][c0];
            al[ks][1] = *(const unsigned*)&su.a.eal[r1][c0];
            al[ks][2] = *(const unsigned*)&su.a.eal[r0][c0 + 8];
            al[ks][3] = *(const unsigned*)&su.a.eal[r1][c0 + 8];
        }
    }
    __syncthreads();

    {
        const int r0 = w8 * 16 + g, r1 = r0 + 8;
#pragma unroll
        for (int j = 0; j < 8; j++) {
            float d0 = 0.f, d1 = 0.f, d2 = 0.f, d3 = 0.f;
#pragma unroll
            for (int ks = 0; ks < 2; ks++) {
                uint4 B = g_bfrag_edge[(size_t)(ks * 8 + j) * 32 + lane];
                mma_bf16(d0, d1, d2, d3, ah[ks][0], ah[ks][1], ah[ks][2], ah[ks][3], B.x, B.y);
                mma_bf16(d0, d1, d2, d3, al[ks][0], al[ks][1], al[ks][2], al[ks][3], B.x, B.y);
                mma_bf16(d0, d1, d2, d3, ah[ks][0], ah[ks][1], ah[ks][2], ah[ks][3], B.z, B.w);
            }
            int c = j * 8 + 2 * t4;
            *(float2*)&su.msg[r0][c] = make_float2(d0, d1);
            *(float2*)&su.msg[r1][c] = make_float2(d2, d3);
        }
    }
    __syncthreads();

    // max-free streaming softmax with 2-way accumulator ILP
    {
        const int local = tid >> 6;
        const int h     = tid & 63;
        const int node  = node0 + local;
        const unsigned vm = smask[local];

        float den0 = 1e-16f, den1 = 0.f, num0 = 0.f, num1 = 0.f;
#pragma unroll
        for (int k = 0; k < KNB; k += 2) {
            bool v0 = (vm >> k) & 1;
            bool v1 = (vm >> (k + 1)) & 1;
            float p0 = su.msg[local * 32 + k][h];
            float p1 = su.msg[local * 32 + k + 1][h];
            float x0 = 0.f, x1 = 0.f;
            if (v0) x0 = g_src[(size_t)ss_[local][k] + h];
            if (v1) x1 = g_src[(size_t)ss_[local][k + 1] + h];
            float m0 = fmaxf(p0 + x0, 0.f) + 1e-7f;
            float m1 = fmaxf(p1 + x1, 0.f) + 1e-7f;
            float a0 = v0 ? __expf(m0) : 0.f;
            float a1 = v1 ? __expf(m1) : 0.f;
            den0 += a0;
            den1 += a1;
            num0 = fmaf(m0, a0, num0);
            num1 = fmaf(m1, a1, num1);
        }

        if (node < n) {
            float dstf = g_dst[(size_t)node * H + h];
            g_out[(size_t)node * H + h] = (num0 + num1) / (den0 + den1) + dstf;
        }
    }
}

// =====================================================================
// Kernel C: g_h = g_out @ w1.T via tensor MMA + fused BN partial stats.
// =====================================================================
__global__ void __launch_bounds__(256)
mlp1_kernel(int n)
{
    __shared__ __align__(16) __nv_bfloat16 ash[128][72];
    __shared__ __align__(16) __nv_bfloat16 asl[128][72];
    __shared__ float rs [4][128];
    __shared__ float rs2[4][128];
    const int tid = threadIdx.x;
    const int warp = tid >> 5, lane = tid & 31;
    const int rb = warp >> 1, cb = warp & 1;
    const int g = lane >> 2, t4 = lane & 3;
    const int n0 = blockIdx.x * 128;

#pragma unroll
    for (int it = 0; it < 8; it++) {
        int i = tid + it * 256;
        int row = i >> 4, q = i & 15;
        int gn = n0 + row;
        float4 v = make_float4(0.f, 0.f, 0.f, 0.f);
        if (gn < n) v = *(const float4*)&g_out[(size_t)gn * H + q * 4];
        unsigned l0, l1;
        unsigned h0 = pack_split_hi(v.x, v.y, l0);
        unsigned h1 = pack_split_hi(v.z, v.w, l1);
        *(uint2*)&ash[row][q * 4] = make_uint2(h0, h1);
        *(uint2*)&asl[row][q * 4] = make_uint2(l0, l1);
    }
    __syncthreads();

    float acc[2][8][4];
#pragma unroll
    for (int mf = 0; mf < 2; mf++)
#pragma unroll
        for (int j = 0; j < 8; j++)
#pragma unroll
            for (int q = 0; q < 4; q++) acc[mf][j][q] = 0.f;

#pragma unroll
    for (int k16 = 0; k16 < 4; k16++) {
        int c0 = k16 * 16 + 2 * t4;
        unsigned ah[2][4], al[2][4];
#pragma unroll
        for (int mf = 0; mf < 2; mf++) {
            int r0 = rb * 32 + mf * 16 + g;
            ah[mf][0] = *(const unsigned*)&ash[r0][c0];
            ah[mf][1] = *(const unsigned*)&ash[r0 + 8][c0];
            ah[mf][2] = *(const unsigned*)&ash[r0][c0 + 8];
            ah[mf][3] = *(const unsigned*)&ash[r0 + 8][c0 + 8];
            al[mf][0] = *(const unsigned*)&asl[r0][c0];
            al[mf][1] = *(const unsigned*)&asl[r0 + 8][c0];
            al[mf][2] = *(const unsigned*)&asl[r0][c0 + 8];
            al[mf][3] = *(const unsigned*)&asl[r0 + 8][c0 + 8];
        }
#pragma unroll
        for (int j = 0; j < 8; j++) {
            uint4 B = g_bfrag_mlp1[(size_t)(k16 * 16 + cb * 8 + j) * 32 + lane];
#pragma unroll
            for (int mf = 0; mf < 2; mf++) {
                float* d = acc[mf][j];
                mma_bf16(d[0], d[1], d[2], d[3], ah[mf][0], ah[mf][1], ah[mf][2], ah[mf][3], B.x, B.y);
                mma_bf16(d[0], d[1], d[2], d[3], al[mf][0], al[mf][1], al[mf][2], al[mf][3], B.x, B.y);
                mma_bf16(d[0], d[1], d[2], d[3], ah[mf][0], ah[mf][1], ah[mf][2], ah[mf][3], B.z, B.w);
            }
        }
    }

#pragma unroll
    for (int mf = 0; mf < 2; mf++) {
        int r = n0 + rb * 32 + mf * 16 + g;
#pragma unroll
        for (int j = 0; j < 8; j++) {
            int c = cb * 64 + j * 8 + 2 * t4;
            float* d = acc[mf][j];
            if (r < n)     *(float2*)&g_h[(size_t)r * H2 + c]       = make_float2(d[0], d[1]);
            if (r + 8 < n) *(float2*)&g_h[(size_t)(r + 8) * H2 + c] = make_float2(d[2], d[3]);
        }
    }

#pragma unroll
    for (int j = 0; j < 8; j++) {
        float s0 = 0.f, s1 = 0.f, q0 = 0.f, q1 = 0.f;
#pragma unroll
        for (int mf = 0; mf < 2; mf++) {
            float* d = acc[mf][j];
            s0 += d[0] + d[2];
            s1 += d[1] + d[3];
            q0 += d[0] * d[0] + d[2] * d[2];
            q1 += d[1] * d[1] + d[3] * d[3];
        }
#pragma unroll
        for (int off = 4; off < 32; off <<= 1) {
            s0 += __shfl_xor_sync(0xffffffffu, s0, off);
            s1 += __shfl_xor_sync(0xffffffffu, s1, off);
            q0 += __shfl_xor_sync(0xffffffffu, q0, off);
            q1 += __shfl_xor_sync(0xffffffffu, q1, off);
        }
        if (g == 0) {
            int c = cb * 64 + j * 8 + 2 * t4;
            rs [rb][c]     = s0;
            rs [rb][c + 1] = s1;
            rs2[rb][c]     = q0;
            rs2[rb][c + 1] = q1;
        }
    }
    __syncthreads();
    if (tid < 128) {
        float s  = rs [0][tid] + rs [1][tid] + rs [2][tid] + rs [3][tid];
        float s2 = rs2[0][tid] + rs2[1][tid] + rs2[2][tid] + rs2[3][tid];
        g_part[(size_t)blockIdx.x * H2 + tid]                      = s;
        g_part[(size_t)NBMAX * H2 + (size_t)blockIdx.x * H2 + tid] = s2;
    }
}

// =====================================================================
// Kernel D: single-kernel BN fold. grid = 128, 512 threads, deterministic.
// =====================================================================
__global__ void __launch_bounds__(512)
fold_kernel(const float* __restrict__ gamma, const float* __restrict__ beta,
            int n, int nb)
{
    __shared__ float sh[512], sh2[512];
    const int c = blockIdx.x;
    const int t = threadIdx.x;
    float s = 0.f, s2 = 0.f;
    if (t < nb) {
        s  = g_part[(size_t)t * H2 + c];
        s2 = g_part[(size_t)NBMAX * H2 + (size_t)t * H2 + c];
    }
    sh[t] = s; sh2[t] = s2;
    __syncthreads();
#pragma unroll
    for (int off = 256; off > 0; off >>= 1) {
        if (t < off) { sh[t] += sh[t + off]; sh2[t] += sh2[t + off]; }
        __syncthreads();
    }
    if (t == 0) {
        float inv_n = 1.f / (float)n;
        float mean  = sh[0] * inv_n;
        float var   = sh2[0] * inv_n - mean * mean;
        float sc    = gamma[c] * rsqrtf(var + 1e-5f);
        g_sb[c]      = sc;
        g_sb[H2 + c] = beta[c] - mean * sc;
    }
}

// =====================================================================
// Kernel E: out = relu(bn(g_h)) @ w2.T via tensor MMA. tile 128 x 64.
// =====================================================================
__global__ void __launch_bounds__(256)
mlp2_kernel(float* __restrict__ outp, int n)
{
    __shared__ __align__(16) __nv_bfloat16 ash[128][40];
    __shared__ __align__(16) __nv_bfloat16 asl[128][40];
    const int tid = threadIdx.x;
    const int warp = tid >> 5, lane = tid & 31;
    const int rb = warp >> 1, cb = warp & 1;
    const int g = lane >> 2, t4 = lane & 3;
    const int n0 = blockIdx.x * 128;

    float acc[2][4][4];
#pragma unroll
    for (int mf = 0; mf < 2; mf++)
#pragma unroll
        for (int j = 0; j < 4; j++)
#pragma unroll
            for (int q = 0; q < 4; q++) acc[mf][j][q] = 0.f;

    for (int dt = 0; dt < 128; dt += 32) {
#pragma unroll
        for (int it = 0; it < 4; it++) {
            int i = tid + it * 256;
            int row = i >> 3, q = i & 7;
            int gn = n0 + row;
            int d  = dt + q * 4;
            float4 v = make_float4(0.f, 0.f, 0.f, 0.f);
            if (gn < n) v = *(const float4*)&g_h[(size_t)gn * H2 + d];
            float4 sc = *(const float4*)&g_sb[d];
            float4 bi = *(const float4*)&g_sb[H2 + d];
            float r0 = fmaxf(fmaf(v.x, sc.x, bi.x), 0.f);
            float r1 = fmaxf(fmaf(v.y, sc.y, bi.y), 0.f);
            float r2 = fmaxf(fmaf(v.z, sc.z, bi.z), 0.f);
            float r3 = fmaxf(fmaf(v.w, sc.w, bi.w), 0.f);
            unsigned l0, l1;
            unsigned h0 = pack_split_hi(r0, r1, l0);
            unsigned h1 = pack_split_hi(r2, r3, l1);
            *(uint2*)&ash[row][q * 4] = make_uint2(h0, h1);
            *(uint2*)&asl[row][q * 4] = make_uint2(l0, l1);
        }
        __syncthreads();

#pragma unroll
        for (int ks = 0; ks < 2; ks++) {
            int k16 = (dt >> 4) + ks;
            int c0 = ks * 16 + 2 * t4;
            unsigned ah[2][4], al[2][4];
#pragma unroll
            for (int mf = 0; mf < 2; mf++) {
                int r0 = rb * 32 + mf * 16 + g;
                ah[mf][0] = *(const unsigned*)&ash[r0][c0];
                ah[mf][1] = *(const unsigned*)&ash[r0 + 8][c0];
                ah[mf][2] = *(const unsigned*)&ash[r0][c0 + 8];
                ah[mf][3] = *(const unsigned*)&ash[r0 + 8][c0 + 8];
                al[mf][0] = *(const unsigned*)&asl[r0][c0];
                al[mf][1] = *(const unsigned*)&asl[r0 + 8][c0];
                al[mf][2] = *(const unsigned*)&asl[r0][c0 + 8];
                al[mf][3] = *(const unsigned*)&asl[r0 + 8][c0 + 8];
            }
#pragma unroll
            for (int j = 0; j < 4; j++) {
                uint4 B = g_bfrag_mlp2[(size_t)(k16 * 8 + cb * 4 + j) * 32 + lane];
#pragma unroll
                for (int mf = 0; mf < 2; mf++) {
                    float* d = acc[mf][j];
                    mma_bf16(d[0], d[1], d[2], d[3], ah[mf][0], ah[mf][1], ah[mf][2], ah[mf][3], B.x, B.y);
                    mma_bf16(d[0], d[1], d[2], d[3], al[mf][0], al[mf][1], al[mf][2], al[mf][3], B.x, B.y);
                    mma_bf16(d[0], d[1], d[2], d[3], ah[mf][0], ah[mf][1], ah[mf][2], ah[mf][3], B.z, B.w);
                }
            }
        }
        __syncthreads();
    }

#pragma unroll
    for (int mf = 0; mf < 2; mf++) {
        int r = n0 + rb * 32 + mf * 16 + g;
#pragma unroll
        for (int j = 0; j < 4; j++) {
            int c = cb * 32 + j * 8 + 2 * t4;
            float* d = acc[mf][j];
            if (r < n)     *(float2*)&outp[(size_t)r * H + c]       = make_float2(d[0], d[1]);
            if (r + 8 < n) *(float2*)&outp[(size_t)(r + 8) * H + c] = make_float2(d[2], d[3]);
        }
    }
}

// =====================================================================
extern "C" void kernel_launch(void* const* d_in, const int* in_sizes, int n_in,
                              void* d_out, int out_size)
{
    const float* x      = (const float*)d_in[0];
    const float* ea     = (const float*)d_in[1];
    const float* w_src  = (const float*)d_in[2];
    const float* w_dst  = (const float*)d_in[3];
    const float* w_edge = (const float*)d_in[4];
    const float* w1     = (const float*)d_in[5];
    const float* gamma  = (const float*)d_in[6];
    const float* beta   = (const float*)d_in[7];
    const float* w2     = (const float*)d_in[8];
    const int*   ei     = (const int*)d_in[9];
    const int*   nbr    = (const int*)d_in[10];
    float* outp = (float*)d_out;

    int n = in_sizes[0] / INC;
    if (n > MAXN) n = MAXN;

    int gb128 = (n + 127) / 128;
    prep_a_kernel<<<24, 256>>>(w_src, w_dst, w1);        // launch 1
    proj_kernel  <<<gb128, 256>>>(x, n);                 // launch 2
    prep_b_kernel<<<10, 256>>>(w_edge, w2);              // launch 3
    edge_kernel  <<<(n + 3) / 4, 256>>>(ea, ei, nbr, n); // launch 4 (profiled)
    mlp1_kernel  <<<gb128, 256>>>(n);                    // launch 5
    fold_kernel  <<<128, 512>>>(gamma, beta, n, gb128);  // launch 6
    mlp2_kernel  <<<gb128, 256>>>(outp, n);              // launch 7
}

// round 16
// speedup vs baseline: 1.1570x; 1.0057x over previous
#include <cuda_runtime.h>
#include <cuda_bf16.h>
#include <cstdint>

#define MAXN   50000
#define KNB    32
#define INC    128
#define H      64
#define EDGED  32
#define H2     128
#define NBMAX  391   // ceil(MAXN/128)

// ---------------- scratch (static device memory; no allocation) ----------------
__device__ float g_src [(size_t)MAXN * H];    // x @ w_src.T
__device__ float g_dst [(size_t)MAXN * H];    // x @ w_dst.T
__device__ float g_out [(size_t)MAXN * H];
__device__ float g_h   [(size_t)MAXN * H2];
__device__ float g_part [2 * NBMAX * H2];
__device__ float g_sb  [2 * H2];

// Prepacked B fragments (bf16 hi/lo split, MMA register layout):
// uint4 = {bh0, bh1, bl0, bl1} per lane.
__device__ uint4 g_bfrag_proj[8 * 16 * 32];   // [k16][jb(16)][lane]
__device__ uint4 g_bfrag_mlp2[8 * 8 * 32];    // [k16][jb(8)][lane]
__device__ uint4 g_bfrag_edge[2 * 8 * 32];    // [ks][j(8)][lane]
__device__ uint4 g_bfrag_mlp1[4 * 16 * 32];   // [k16][jb(16)][lane]

// ---------------- helpers ----------------
// bf16 hi/lo split using the packed cvt: 6 instrs/pair, same rn rounding
// as __float2bfloat16 (bit-identical results).
__device__ __forceinline__ unsigned pack_split_hi(float a, float b,
                                                  unsigned& lo_pack) {
    unsigned hi;
    asm("cvt.rn.bf16x2.f32 %0, %1, %2;" : "=r"(hi) : "f"(b), "f"(a));
    float ah = __uint_as_float(hi << 16);
    float bh = __uint_as_float(hi & 0xffff0000u);
    float ra = a - ah;
    float rb = b - bh;
    unsigned lo;
    asm("cvt.rn.bf16x2.f32 %0, %1, %2;" : "=r"(lo) : "f"(rb), "f"(ra));
    lo_pack = lo;
    return hi;
}

__device__ __forceinline__ void mma_bf16(float& d0, float& d1, float& d2, float& d3,
                                         unsigned a0, unsigned a1, unsigned a2, unsigned a3,
                                         unsigned b0, unsigned b1) {
    asm volatile(
        "mma.sync.aligned.m16n8k16.row.col.f32.bf16.bf16.f32 "
        "{%0,%1,%2,%3}, {%4,%5,%6,%7}, {%8,%9}, {%0,%1,%2,%3};"
        : "+f"(d0), "+f"(d1), "+f"(d2), "+f"(d3)
        : "r"(a0), "r"(a1), "r"(a2), "r"(a3), "r"(b0), "r"(b1));
}

// =====================================================================
// Kernel P-a: prepack B fragments for proj + mlp1.
// =====================================================================
__global__ void __launch_bounds__(256)
prep_a_kernel(const float* __restrict__ w_src,
              const float* __restrict__ w_dst,
              const float* __restrict__ w1)
{
    int t = blockIdx.x * 256 + threadIdx.x;
    const float* brow;
    int k, idx;
    uint4* dst;
    if (t < 4096) {                 // proj
        int lane = t & 31, jb = (t >> 5) & 15, k16 = t >> 9;
        int g = lane >> 2, t4 = lane & 3;
        int nn = jb * 8 + g;
        k = k16 * 16 + 2 * t4;
        brow = (nn < 64) ? (w_src + (size_t)nn * 128) : (w_dst + (size_t)(nn - 64) * 128);
        dst = g_bfrag_proj; idx = t;
    } else if (t < 6144) {          // mlp1
        int u = t - 4096;
        int lane = u & 31, jb = (u >> 5) & 15, k16 = u >> 9;
        int g = lane >> 2, t4 = lane & 3;
        int nn = jb * 8 + g;
        k = k16 * 16 + 2 * t4;
        brow = w1 + (size_t)nn * 64;
        dst = g_bfrag_mlp1; idx = u;
    } else return;

    float v0 = brow[k], v1 = brow[k + 1], v8 = brow[k + 8], v9 = brow[k + 9];
    unsigned l0, l1;
    unsigned h0 = pack_split_hi(v0, v1, l0);
    unsigned h1 = pack_split_hi(v8, v9, l1);
    dst[idx] = make_uint4(h0, h1, l0, l1);
}

// =====================================================================
// Kernel P-b: prepack B fragments for edge + mlp2.
// =====================================================================
__global__ void __launch_bounds__(256)
prep_b_kernel(const float* __restrict__ w_edge,
              const float* __restrict__ w2)
{
    int t = blockIdx.x * 256 + threadIdx.x;
    const float* brow;
    int k, idx;
    uint4* dst;
    if (t < 2048) {                 // mlp2
        int lane = t & 31, jb = (t >> 5) & 7, k16 = t >> 8;
        int g = lane >> 2, t4 = lane & 3;
        int nn = jb * 8 + g;
        k = k16 * 16 + 2 * t4;
        brow = w2 + (size_t)nn * 128;
        dst = g_bfrag_mlp2; idx = t;
    } else if (t < 2560) {          // edge
        int u = t - 2048;
        int lane = u & 31, j = (u >> 5) & 7, ks = u >> 8;
        int g = lane >> 2, t4 = lane & 3;
        int nn = j * 8 + g;
        k = ks * 16 + 2 * t4;
        brow = w_edge + (size_t)nn * 32;
        dst = g_bfrag_edge; idx = u;
    } else return;

    float v0 = brow[k], v1 = brow[k + 1], v8 = brow[k + 8], v9 = brow[k + 9];
    unsigned l0, l1;
    unsigned h0 = pack_split_hi(v0, v1, l0);
    unsigned h1 = pack_split_hi(v8, v9, l1);
    dst[idx] = make_uint4(h0, h1, l0, l1);
}

// =====================================================================
// Kernel A: proj via tensor MMA. tile 128 nodes x 128 ch, 8 warps (4 rb x 2 cb).
// cb=0 -> g_src channels, cb=1 -> g_dst channels.
// =====================================================================
__global__ void __launch_bounds__(256)
proj_kernel(const float* __restrict__ x, int n)
{
    __shared__ __align__(16) __nv_bfloat16 ash[128][40];
    __shared__ __align__(16) __nv_bfloat16 asl[128][40];
    const int tid = threadIdx.x;
    const int warp = tid >> 5, lane = tid & 31;
    const int rb = warp >> 1, cb = warp & 1;
    const int g = lane >> 2, t4 = lane & 3;
    const int n0 = blockIdx.x * 128;

    float acc[2][8][4];
#pragma unroll
    for (int mf = 0; mf < 2; mf++)
#pragma unroll
        for (int j = 0; j < 8; j++)
#pragma unroll
            for (int q = 0; q < 4; q++) acc[mf][j][q] = 0.f;

    for (int dt = 0; dt < 128; dt += 32) {
#pragma unroll
        for (int it = 0; it < 4; it++) {
            int i = tid + it * 256;
            int row = i >> 3, q = i & 7;
            int gn = n0 + row;
            float4 v = make_float4(0.f, 0.f, 0.f, 0.f);
            if (gn < n) v = *(const float4*)&x[(size_t)gn * 128 + dt + q * 4];
            unsigned l0, l1;
            unsigned h0 = pack_split_hi(v.x, v.y, l0);
            unsigned h1 = pack_split_hi(v.z, v.w, l1);
            *(uint2*)&ash[row][q * 4] = make_uint2(h0, h1);
            *(uint2*)&asl[row][q * 4] = make_uint2(l0, l1);
        }
        __syncthreads();

#pragma unroll
        for (int ks = 0; ks < 2; ks++) {
            int k16 = (dt >> 4) + ks;
            int c0 = ks * 16 + 2 * t4;
            unsigned ah[2][4], al[2][4];
#pragma unroll
            for (int mf = 0; mf < 2; mf++) {
                int r0 = rb * 32 + mf * 16 + g;
                ah[mf][0] = *(const unsigned*)&ash[r0][c0];
                ah[mf][1] = *(const unsigned*)&ash[r0 + 8][c0];
                ah[mf][2] = *(const unsigned*)&ash[r0][c0 + 8];
                ah[mf][3] = *(const unsigned*)&ash[r0 + 8][c0 + 8];
                al[mf][0] = *(const unsigned*)&asl[r0][c0];
                al[mf][1] = *(const unsigned*)&asl[r0 + 8][c0];
                al[mf][2] = *(const unsigned*)&asl[r0][c0 + 8];
                al[mf][3] = *(const unsigned*)&asl[r0 + 8][c0 + 8];
            }
#pragma unroll
            for (int j = 0; j < 8; j++) {
                uint4 B = g_bfrag_proj[(size_t)(k16 * 16 + cb * 8 + j) * 32 + lane];
#pragma unroll
                for (int mf = 0; mf < 2; mf++) {
                    float* d = acc[mf][j];
                    mma_bf16(d[0], d[1], d[2], d[3], ah[mf][0], ah[mf][1], ah[mf][2], ah[mf][3], B.x, B.y);
                    mma_bf16(d[0], d[1], d[2], d[3], al[mf][0], al[mf][1], al[mf][2], al[mf][3], B.x, B.y);
                    mma_bf16(d[0], d[1], d[2], d[3], ah[mf][0], ah[mf][1], ah[mf][2], ah[mf][3], B.z, B.w);
                }
            }
        }
        __syncthreads();
    }

    float* obase = cb ? g_dst : g_src;
#pragma unroll
    for (int mf = 0; mf < 2; mf++) {
        int r = n0 + rb * 32 + mf * 16 + g;
#pragma unroll
        for (int j = 0; j < 8; j++) {
            int c = j * 8 + 2 * t4;
            float* d = acc[mf][j];
            if (r < n)     *(float2*)&obase[(size_t)r * H + c]       = make_float2(d[0], d[1]);
            if (r + 8 < n) *(float2*)&obase[(size_t)(r + 8) * H + c] = make_float2(d[2], d[3]);
        }
    }
}

// =====================================================================
// Kernel B: edge MLP (tensor MMA) + max-free streaming softmax.
// 4 nodes/block, 256 thr, (256,5). R16: msg stored TRANSPOSED
// (msgT[local][ch][k], stride 36 -> conflict-free scatter stores AND
// vectorized float4 softmax reads: 32 LDS.32 -> 8 LDS.128), 4-way
// accumulator ILP with 4 xj gathers in flight.
// =====================================================================
__global__ void __launch_bounds__(256, 5)
edge_kernel(const float* __restrict__ ea,
            const int*   __restrict__ ei,
            const int*   __restrict__ nbr,
            int n)
{
    __shared__ union {
        struct { __nv_bfloat16 eah[128][40]; __nv_bfloat16 eal[128][40]; } a;
        __align__(16) float msgT[4][64][36];   // [local][ch][k] (+4 pad)
    } su;
    __shared__ int      se_[4][KNB];
    __shared__ int      ss_[4][KNB];   // holds ei[e]*H (prescaled element offset)
    __shared__ unsigned smask[4];

    const int tid   = threadIdx.x;
    const int node0 = blockIdx.x * 4;

    if (tid < 128) {
        int local = tid >> 5, k = tid & 31;
        int node = node0 + local;
        int e = (node < n) ? nbr[(size_t)node * KNB + k] : -1;
        se_[local][k] = e;
        ss_[local][k] = (e >= 0) ? (ei[e] * H) : 0;
        unsigned msk = __ballot_sync(0xffffffffu, e >= 0);
        if (k == 0) smask[local] = msk;
    }
    __syncthreads();

    // batched staging: all 4 gather loads in flight, then convert+store
    {
        float4 v[4];
#pragma unroll
        for (int it = 0; it < 4; it++) {
            int i = tid + it * 256;
            int row = i >> 3, q = i & 7;
            int local = row >> 5, k = row & 31;
            v[it] = make_float4(0.f, 0.f, 0.f, 0.f);
            if ((smask[local] >> k) & 1)
                v[it] = *(const float4*)&ea[(size_t)se_[local][k] * EDGED + q * 4];
        }
#pragma unroll
        for (int it = 0; it < 4; it++) {
            int i = tid + it * 256;
            int row = i >> 3, q = i & 7;
            unsigned l0, l1;
            unsigned h0 = pack_split_hi(v[it].x, v[it].y, l0);
            unsigned h1 = pack_split_hi(v[it].z, v[it].w, l1);
            *(uint2*)&su.a.eah[row][q * 4] = make_uint2(h0, h1);
            *(uint2*)&su.a.eal[row][q * 4] = make_uint2(l0, l1);
        }
    }
    __syncthreads();

    const int w8 = tid >> 5, lane = tid & 31;
    const int g = lane >> 2, t4 = lane & 3;
    unsigned ah[2][4], al[2][4];
    {
        const int r0 = w8 * 16 + g, r1 = r0 + 8;
#pragma unroll
        for (int ks = 0; ks < 2; ks++) {
            int c0 = ks * 16 + 2 * t4;
            ah[ks][0] = *(const unsigned*)&su.a.eah[r0][c0];
            ah[ks][1] = *(const unsigned*)&su.a.eah[r1][c0];
            ah[ks][2] = *(const unsigned*)&su.a.eah[r0][c0 + 8];
            ah[ks][3] = *(const unsigned*)&su.a.eah[r1][c0 + 8];
            al[ks][0] = *(const unsigned*)&su.a.eal[r0][c0];
            al[ks][1] = *(const unsigned*)&su.a.eal[r1][c0];
            al[ks][2] = *(const unsigned*)&su.a.eal[r0][c0 + 8];
            al[ks][3] = *(const unsigned*)&su.a.eal[r1][c0 + 8];
        }
    }
    __syncthreads();   // a-tile dead; msgT may overwrite

    // MMA phase: write results transposed into msgT[local][ch][k]
    {
        const int loc = w8 >> 1;
        const int kk  = (w8 & 1) * 16 + g;   // k index of r0 within local's 32
        float* base = &su.msgT[loc][0][0];
#pragma unroll
        for (int j = 0; j < 8; j++) {
            float d0 = 0.f, d1 = 0.f, d2 = 0.f, d3 = 0.f;
#pragma unroll
            for (int ks = 0; ks < 2; ks++) {
                uint4 B = g_bfrag_edge[(size_t)(ks * 8 + j) * 32 + lane];
                mma_bf16(d0, d1, d2, d3, ah[ks][0], ah[ks][1], ah[ks][2], ah[ks][3], B.x, B.y);
                mma_bf16(d0, d1, d2, d3, al[ks][0], al[ks][1], al[ks][2], al[ks][3], B.x, B.y);
                mma_bf16(d0, d1, d2, d3, ah[ks][0], ah[ks][1], ah[ks][2], ah[ks][3], B.z, B.w);
            }
            int c = j * 8 + 2 * t4;
            base[c * 36 + kk]           = d0;   // (ch=c,   k=kk)
            base[(c + 1) * 36 + kk]     = d1;   // (ch=c+1, k=kk)
            base[c * 36 + kk + 8]       = d2;   // (ch=c,   k=kk+8)
            base[(c + 1) * 36 + kk + 8] = d3;   // (ch=c+1, k=kk+8)
        }
    }
    __syncthreads();

    // max-free streaming softmax: thread = (local node, channel h),
    // vectorized msg reads (float4) + 4-way accumulators.
    {
        const int local = tid >> 6;
        const int h     = tid & 63;
        const int node  = node0 + local;
        const unsigned vm = smask[local];
        const float* row = &su.msgT[local][h][0];

        float den0 = 1e-16f, den1 = 0.f, den2 = 0.f, den3 = 0.f;
        float num0 = 0.f, num1 = 0.f, num2 = 0.f, num3 = 0.f;
#pragma unroll
        for (int kq = 0; kq < 8; kq++) {
            int k = kq * 4;
            float4 p = *(const float4*)&row[k];
            bool v0 = (vm >> k) & 1;
            bool v1 = (vm >> (k + 1)) & 1;
            bool v2 = (vm >> (k + 2)) & 1;
            bool v3 = (vm >> (k + 3)) & 1;
            float x0 = 0.f, x1 = 0.f, x2 = 0.f, x3 = 0.f;
            if (v0) x0 = g_src[(size_t)ss_[local][k]     + h];
            if (v1) x1 = g_src[(size_t)ss_[local][k + 1] + h];
            if (v2) x2 = g_src[(size_t)ss_[local][k + 2] + h];
            if (v3) x3 = g_src[(size_t)ss_[local][k + 3] + h];
            float m0 = fmaxf(p.x + x0, 0.f) + 1e-7f;
            float m1 = fmaxf(p.y + x1, 0.f) + 1e-7f;
            float m2 = fmaxf(p.z + x2, 0.f) + 1e-7f;
            float m3 = fmaxf(p.w + x3, 0.f) + 1e-7f;
            float a0 = v0 ? __expf(m0) : 0.f;
            float a1 = v1 ? __expf(m1) : 0.f;
            float a2 = v2 ? __expf(m2) : 0.f;
            float a3 = v3 ? __expf(m3) : 0.f;
            den0 += a0; den1 += a1; den2 += a2; den3 += a3;
            num0 = fmaf(m0, a0, num0);
            num1 = fmaf(m1, a1, num1);
            num2 = fmaf(m2, a2, num2);
            num3 = fmaf(m3, a3, num3);
        }

        if (node < n) {
            float dstf = g_dst[(size_t)node * H + h];
            float den = (den0 + den1) + (den2 + den3);
            float num = (num0 + num1) + (num2 + num3);
            g_out[(size_t)node * H + h] = num / den + dstf;
        }
    }
}

// =====================================================================
// Kernel C: g_h = g_out @ w1.T via tensor MMA + fused BN partial stats.
// =====================================================================
__global__ void __launch_bounds__(256)
mlp1_kernel(int n)
{
    __shared__ __align__(16) __nv_bfloat16 ash[128][72];
    __shared__ __align__(16) __nv_bfloat16 asl[128][72];
    __shared__ float rs [4][128];
    __shared__ float rs2[4][128];
    const int tid = threadIdx.x;
    const int warp = tid >> 5, lane = tid & 31;
    const int rb = warp >> 1, cb = warp & 1;
    const int g = lane >> 2, t4 = lane & 3;
    const int n0 = blockIdx.x * 128;

#pragma unroll
    for (int it = 0; it < 8; it++) {
        int i = tid + it * 256;
        int row = i >> 4, q = i & 15;
        int gn = n0 + row;
        float4 v = make_float4(0.f, 0.f, 0.f, 0.f);
        if (gn < n) v = *(const float4*)&g_out[(size_t)gn * H + q * 4];
        unsigned l0, l1;
        unsigned h0 = pack_split_hi(v.x, v.y, l0);
        unsigned h1 = pack_split_hi(v.z, v.w, l1);
        *(uint2*)&ash[row][q * 4] = make_uint2(h0, h1);
        *(uint2*)&asl[row][q * 4] = make_uint2(l0, l1);
    }
    __syncthreads();

    float acc[2][8][4];
#pragma unroll
    for (int mf = 0; mf < 2; mf++)
#pragma unroll
        for (int j = 0; j < 8; j++)
#pragma unroll
            for (int q = 0; q < 4; q++) acc[mf][j][q] = 0.f;

#pragma unroll
    for (int k16 = 0; k16 < 4; k16++) {
        int c0 = k16 * 16 + 2 * t4;
        unsigned ah[2][4], al[2][4];
#pragma unroll
        for (int mf = 0; mf < 2; mf++) {
            int r0 = rb * 32 + mf * 16 + g;
            ah[mf][0] = *(const unsigned*)&ash[r0][c0];
            ah[mf][1] = *(const unsigned*)&ash[r0 + 8][c0];
            ah[mf][2] = *(const unsigned*)&ash[r0][c0 + 8];
            ah[mf][3] = *(const unsigned*)&ash[r0 + 8][c0 + 8];
            al[mf][0] = *(const unsigned*)&asl[r0][c0];
            al[mf][1] = *(const unsigned*)&asl[r0 + 8][c0];
            al[mf][2] = *(const unsigned*)&asl[r0][c0 + 8];
            al[mf][3] = *(const unsigned*)&asl[r0 + 8][c0 + 8];
        }
#pragma unroll
        for (int j = 0; j < 8; j++) {
            uint4 B = g_bfrag_mlp1[(size_t)(k16 * 16 + cb * 8 + j) * 32 + lane];
#pragma unroll
            for (int mf = 0; mf < 2; mf++) {
                float* d = acc[mf][j];
                mma_bf16(d[0], d[1], d[2], d[3], ah[mf][0], ah[mf][1], ah[mf][2], ah[mf][3], B.x, B.y);
                mma_bf16(d[0], d[1], d[2], d[3], al[mf][0], al[mf][1], al[mf][2], al[mf][3], B.x, B.y);
                mma_bf16(d[0], d[1], d[2], d[3], ah[mf][0], ah[mf][1], ah[mf][2], ah[mf][3], B.z, B.w);
            }
        }
    }

#pragma unroll
    for (int mf = 0; mf < 2; mf++) {
        int r = n0 + rb * 32 + mf * 16 + g;
#pragma unroll
        for (int j = 0; j < 8; j++) {
            int c = cb * 64 + j * 8 + 2 * t4;
            float* d = acc[mf][j];
            if (r < n)     *(float2*)&g_h[(size_t)r * H2 + c]       = make_float2(d[0], d[1]);
            if (r + 8 < n) *(float2*)&g_h[(size_t)(r + 8) * H2 + c] = make_float2(d[2], d[3]);
        }
    }

#pragma unroll
    for (int j = 0; j < 8; j++) {
        float s0 = 0.f, s1 = 0.f, q0 = 0.f, q1 = 0.f;
#pragma unroll
        for (int mf = 0; mf < 2; mf++) {
            float* d = acc[mf][j];
            s0 += d[0] + d[2];
            s1 += d[1] + d[3];
            q0 += d[0] * d[0] + d[2] * d[2];
            q1 += d[1] * d[1] + d[3] * d[3];
        }
#pragma unroll
        for (int off = 4; off < 32; off <<= 1) {
            s0 += __shfl_xor_sync(0xffffffffu, s0, off);
            s1 += __shfl_xor_sync(0xffffffffu, s1, off);
            q0 += __shfl_xor_sync(0xffffffffu, q0, off);
            q1 += __shfl_xor_sync(0xffffffffu, q1, off);
        }
        if (g == 0) {
            int c = cb * 64 + j * 8 + 2 * t4;
            rs [rb][c]     = s0;
            rs [rb][c + 1] = s1;
            rs2[rb][c]     = q0;
            rs2[rb][c + 1] = q1;
        }
    }
    __syncthreads();
    if (tid < 128) {
        float s  = rs [0][tid] + rs [1][tid] + rs [2][tid] + rs [3][tid];
        float s2 = rs2[0][tid] + rs2[1][tid] + rs2[2][tid] + rs2[3][tid];
        g_part[(size_t)blockIdx.x * H2 + tid]                      = s;
        g_part[(size_t)NBMAX * H2 + (size_t)blockIdx.x * H2 + tid] = s2;
    }
}

// =====================================================================
// Kernel D: single-kernel BN fold. grid = 128, 512 threads, deterministic.
// =====================================================================
__global__ void __launch_bounds__(512)
fold_kernel(const float* __restrict__ gamma, const float* __restrict__ beta,
            int n, int nb)
{
    __shared__ float sh[512], sh2[512];
    const int c = blockIdx.x;
    const int t = threadIdx.x;
    float s = 0.f, s2 = 0.f;
    if (t < nb) {
        s  = g_part[(size_t)t * H2 + c];
        s2 = g_part[(size_t)NBMAX * H2 + (size_t)t * H2 + c];
    }
    sh[t] = s; sh2[t] = s2;
    __syncthreads();
#pragma unroll
    for (int off = 256; off > 0; off >>= 1) {
        if (t < off) { sh[t] += sh[t + off]; sh2[t] += sh2[t + off]; }
        __syncthreads();
    }
    if (t == 0) {
        float inv_n = 1.f / (float)n;
        float mean  = sh[0] * inv_n;
        float var   = sh2[0] * inv_n - mean * mean;
        float sc    = gamma[c] * rsqrtf(var + 1e-5f);
        g_sb[c]      = sc;
        g_sb[H2 + c] = beta[c] - mean * sc;
    }
}

// =====================================================================
// Kernel E: out = relu(bn(g_h)) @ w2.T via tensor MMA. tile 128 x 64.
// =====================================================================
__global__ void __launch_bounds__(256)
mlp2_kernel(float* __restrict__ outp, int n)
{
    __shared__ __align__(16) __nv_bfloat16 ash[128][40];
    __shared__ __align__(16) __nv_bfloat16 asl[128][40];
    const int tid = threadIdx.x;
    const int warp = tid >> 5, lane = tid & 31;
    const int rb = warp >> 1, cb = warp & 1;
    const int g = lane >> 2, t4 = lane & 3;
    const int n0 = blockIdx.x * 128;

    float acc[2][4][4];
#pragma unroll
    for (int mf = 0; mf < 2; mf++)
#pragma unroll
        for (int j = 0; j < 4; j++)
#pragma unroll
            for (int q = 0; q < 4; q++) acc[mf][j][q] = 0.f;

    for (int dt = 0; dt < 128; dt += 32) {
#pragma unroll
        for (int it = 0; it < 4; it++) {
            int i = tid + it * 256;
            int row = i >> 3, q = i & 7;
            int gn = n0 + row;
            int d  = dt + q * 4;
            float4 v = make_float4(0.f, 0.f, 0.f, 0.f);
            if (gn < n) v = *(const float4*)&g_h[(size_t)gn * H2 + d];
            float4 sc = *(const float4*)&g_sb[d];
            float4 bi = *(const float4*)&g_sb[H2 + d];
            float r0 = fmaxf(fmaf(v.x, sc.x, bi.x), 0.f);
            float r1 = fmaxf(fmaf(v.y, sc.y, bi.y), 0.f);
            float r2 = fmaxf(fmaf(v.z, sc.z, bi.z), 0.f);
            float r3 = fmaxf(fmaf(v.w, sc.w, bi.w), 0.f);
            unsigned l0, l1;
            unsigned h0 = pack_split_hi(r0, r1, l0);
            unsigned h1 = pack_split_hi(r2, r3, l1);
            *(uint2*)&ash[row][q * 4] = make_uint2(h0, h1);
            *(uint2*)&asl[row][q * 4] = make_uint2(l0, l1);
        }
        __syncthreads();

#pragma unroll
        for (int ks = 0; ks < 2; ks++) {
            int k16 = (dt >> 4) + ks;
            int c0 = ks * 16 + 2 * t4;
            unsigned ah[2][4], al[2][4];
#pragma unroll
            for (int mf = 0; mf < 2; mf++) {
                int r0 = rb * 32 + mf * 16 + g;
                ah[mf][0] = *(const unsigned*)&ash[r0][c0];
                ah[mf][1] = *(const unsigned*)&ash[r0 + 8][c0];
                ah[mf][2] = *(const unsigned*)&ash[r0][c0 + 8];
                ah[mf][3] = *(const unsigned*)&ash[r0 + 8][c0 + 8];
                al[mf][0] = *(const unsigned*)&asl[r0][c0];
                al[mf][1] = *(const unsigned*)&asl[r0 + 8][c0];
                al[mf][2] = *(const unsigned*)&asl[r0][c0 + 8];
                al[mf][3] = *(const unsigned*)&asl[r0 + 8][c0 + 8];
            }
#pragma unroll
            for (int j = 0; j < 4; j++) {
                uint4 B = g_bfrag_mlp2[(size_t)(k16 * 8 + cb * 4 + j) * 32 + lane];
#pragma unroll
                for (int mf = 0; mf < 2; mf++) {
                    float* d = acc[mf][j];
                    mma_bf16(d[0], d[1], d[2], d[3], ah[mf][0], ah[mf][1], ah[mf][2], ah[mf][3], B.x, B.y);
                    mma_bf16(d[0], d[1], d[2], d[3], al[mf][0], al[mf][1], al[mf][2], al[mf][3], B.x, B.y);
                    mma_bf16(d[0], d[1], d[2], d[3], ah[mf][0], ah[mf][1], ah[mf][2], ah[mf][3], B.z, B.w);
                }
            }
        }
        __syncthreads();
    }

#pragma unroll
    for (int mf = 0; mf < 2; mf++) {
        int r = n0 + rb * 32 + mf * 16 + g;
#pragma unroll
        for (int j = 0; j < 4; j++) {
            int c = cb * 32 + j * 8 + 2 * t4;
            float* d = acc[mf][j];
            if (r < n)     *(float2*)&outp[(size_t)r * H + c]       = make_float2(d[0], d[1]);
            if (r + 8 < n) *(float2*)&outp[(size_t)(r + 8) * H + c] = make_float2(d[2], d[3]);
        }
    }
}

// =====================================================================
extern "C" void kernel_launch(void* const* d_in, const int* in_sizes, int n_in,
                              void* d_out, int out_size)
{
    const float* x      = (const float*)d_in[0];
    const float* ea     = (const float*)d_in[1];
    const float* w_src  = (const float*)d_in[2];
    const float* w_dst  = (const float*)d_in[3];
    const float* w_edge = (const float*)d_in[4];
    const float* w1     = (const float*)d_in[5];
    const float* gamma  = (const float*)d_in[6];
    const float* beta   = (const float*)d_in[7];
    const float* w2     = (const float*)d_in[8];
    const int*   ei     = (const int*)d_in[9];
    const int*   nbr    = (const int*)d_in[10];
    float* outp = (float*)d_out;

    int n = in_sizes[0] / INC;
    if (n > MAXN) n = MAXN;

    int gb128 = (n + 127) / 128;
    prep_a_kernel<<<24, 256>>>(w_src, w_dst, w1);        // launch 1
    proj_kernel  <<<gb128, 256>>>(x, n);                 // launch 2
    prep_b_kernel<<<10, 256>>>(w_edge, w2);              // launch 3
    edge_kernel  <<<(n + 3) / 4, 256>>>(ea, ei, nbr, n); // launch 4 (profiled)
    mlp1_kernel  <<<gb128, 256>>>(n);                    // launch 5
    fold_kernel  <<<128, 512>>>(gamma, beta, n, gb128);  // launch 6
    mlp2_kernel  <<<gb128, 256>>>(outp, n);              // launch 7
}

// round 17
// speedup vs baseline: 1.1966x; 1.0342x over previous
#include <cuda_runtime.h>
#include <cuda_bf16.h>
#include <cstdint>

#define MAXN   50000
#define KNB    32
#define INC    128
#define H      64
#define EDGED  32
#define H2     128
#define NBMAX  391   // ceil(MAXN/128)

// ---------------- scratch (static device memory; no allocation) ----------------
__device__ float g_src [(size_t)MAXN * H];    // x @ w_src.T
__device__ float g_dst [(size_t)MAXN * H];    // x @ w_dst.T
__device__ float g_out [(size_t)MAXN * H];
__device__ float g_h   [(size_t)MAXN * H2];
__device__ float g_part [2 * NBMAX * H2];
__device__ float g_sb  [2 * H2];

// Prepacked B fragments (bf16 hi/lo split, MMA register layout):
// uint4 = {bh0, bh1, bl0, bl1} per lane.
__device__ uint4 g_bfrag_proj[8 * 16 * 32];   // [k16][jb(16)][lane]
__device__ uint4 g_bfrag_mlp2[8 * 8 * 32];    // [k16][jb(8)][lane]
__device__ uint4 g_bfrag_edge[2 * 8 * 32];    // [ks][j(8)][lane]
__device__ uint4 g_bfrag_mlp1[4 * 16 * 32];   // [k16][jb(16)][lane]

// ---------------- helpers ----------------
// bf16 hi/lo split using the packed cvt: 6 instrs/pair, same rn rounding
// as __float2bfloat16 (bit-identical results).
__device__ __forceinline__ unsigned pack_split_hi(float a, float b,
                                                  unsigned& lo_pack) {
    unsigned hi;
    asm("cvt.rn.bf16x2.f32 %0, %1, %2;" : "=r"(hi) : "f"(b), "f"(a));
    float ah = __uint_as_float(hi << 16);
    float bh = __uint_as_float(hi & 0xffff0000u);
    float ra = a - ah;
    float rb = b - bh;
    unsigned lo;
    asm("cvt.rn.bf16x2.f32 %0, %1, %2;" : "=r"(lo) : "f"(rb), "f"(ra));
    lo_pack = lo;
    return hi;
}

__device__ __forceinline__ void mma_bf16(float& d0, float& d1, float& d2, float& d3,
                                         unsigned a0, unsigned a1, unsigned a2, unsigned a3,
                                         unsigned b0, unsigned b1) {
    asm volatile(
        "mma.sync.aligned.m16n8k16.row.col.f32.bf16.bf16.f32 "
        "{%0,%1,%2,%3}, {%4,%5,%6,%7}, {%8,%9}, {%0,%1,%2,%3};"
        : "+f"(d0), "+f"(d1), "+f"(d2), "+f"(d3)
        : "r"(a0), "r"(a1), "r"(a2), "r"(a3), "r"(b0), "r"(b1));
}

// =====================================================================
// Kernel P-a: prepack B fragments for proj + mlp1.
// =====================================================================
__global__ void __launch_bounds__(256)
prep_a_kernel(const float* __restrict__ w_src,
              const float* __restrict__ w_dst,
              const float* __restrict__ w1)
{
    int t = blockIdx.x * 256 + threadIdx.x;
    const float* brow;
    int k, idx;
    uint4* dst;
    if (t < 4096) {                 // proj
        int lane = t & 31, jb = (t >> 5) & 15, k16 = t >> 9;
        int g = lane >> 2, t4 = lane & 3;
        int nn = jb * 8 + g;
        k = k16 * 16 + 2 * t4;
        brow = (nn < 64) ? (w_src + (size_t)nn * 128) : (w_dst + (size_t)(nn - 64) * 128);
        dst = g_bfrag_proj; idx = t;
    } else if (t < 6144) {          // mlp1
        int u = t - 4096;
        int lane = u & 31, jb = (u >> 5) & 15, k16 = u >> 9;
        int g = lane >> 2, t4 = lane & 3;
        int nn = jb * 8 + g;
        k = k16 * 16 + 2 * t4;
        brow = w1 + (size_t)nn * 64;
        dst = g_bfrag_mlp1; idx = u;
    } else return;

    float v0 = brow[k], v1 = brow[k + 1], v8 = brow[k + 8], v9 = brow[k + 9];
    unsigned l0, l1;
    unsigned h0 = pack_split_hi(v0, v1, l0);
    unsigned h1 = pack_split_hi(v8, v9, l1);
    dst[idx] = make_uint4(h0, h1, l0, l1);
}

// =====================================================================
// Kernel P-b: prepack B fragments for edge + mlp2.
// =====================================================================
__global__ void __launch_bounds__(256)
prep_b_kernel(const float* __restrict__ w_edge,
              const float* __restrict__ w2)
{
    int t = blockIdx.x * 256 + threadIdx.x;
    const float* brow;
    int k, idx;
    uint4* dst;
    if (t < 2048) {                 // mlp2
        int lane = t & 31, jb = (t >> 5) & 7, k16 = t >> 8;
        int g = lane >> 2, t4 = lane & 3;
        int nn = jb * 8 + g;
        k = k16 * 16 + 2 * t4;
        brow = w2 + (size_t)nn * 128;
        dst = g_bfrag_mlp2; idx = t;
    } else if (t < 2560) {          // edge
        int u = t - 2048;
        int lane = u & 31, j = (u >> 5) & 7, ks = u >> 8;
        int g = lane >> 2, t4 = lane & 3;
        int nn = j * 8 + g;
        k = ks * 16 + 2 * t4;
        brow = w_edge + (size_t)nn * 32;
        dst = g_bfrag_edge; idx = u;
    } else return;

    float v0 = brow[k], v1 = brow[k + 1], v8 = brow[k + 8], v9 = brow[k + 9];
    unsigned l0, l1;
    unsigned h0 = pack_split_hi(v0, v1, l0);
    unsigned h1 = pack_split_hi(v8, v9, l1);
    dst[idx] = make_uint4(h0, h1, l0, l1);
}

// =====================================================================
// Kernel A: proj via tensor MMA. tile 128 nodes x 128 ch, 8 warps (4 rb x 2 cb).
// cb=0 -> g_src channels, cb=1 -> g_dst channels.
// =====================================================================
__global__ void __launch_bounds__(256)
proj_kernel(const float* __restrict__ x, int n)
{
    __shared__ __align__(16) __nv_bfloat16 ash[128][40];
    __shared__ __align__(16) __nv_bfloat16 asl[128][40];
    const int tid = threadIdx.x;
    const int warp = tid >> 5, lane = tid & 31;
    const int rb = warp >> 1, cb = warp & 1;
    const int g = lane >> 2, t4 = lane & 3;
    const int n0 = blockIdx.x * 128;

    float acc[2][8][4];
#pragma unroll
    for (int mf = 0; mf < 2; mf++)
#pragma unroll
        for (int j = 0; j < 8; j++)
#pragma unroll
            for (int q = 0; q < 4; q++) acc[mf][j][q] = 0.f;

    for (int dt = 0; dt < 128; dt += 32) {
#pragma unroll
        for (int it = 0; it < 4; it++) {
            int i = tid + it * 256;
            int row = i >> 3, q = i & 7;
            int gn = n0 + row;
            float4 v = make_float4(0.f, 0.f, 0.f, 0.f);
            if (gn < n) v = *(const float4*)&x[(size_t)gn * 128 + dt + q * 4];
            unsigned l0, l1;
            unsigned h0 = pack_split_hi(v.x, v.y, l0);
            unsigned h1 = pack_split_hi(v.z, v.w, l1);
            *(uint2*)&ash[row][q * 4] = make_uint2(h0, h1);
            *(uint2*)&asl[row][q * 4] = make_uint2(l0, l1);
        }
        __syncthreads();

#pragma unroll
        for (int ks = 0; ks < 2; ks++) {
            int k16 = (dt >> 4) + ks;
            int c0 = ks * 16 + 2 * t4;
            unsigned ah[2][4], al[2][4];
#pragma unroll
            for (int mf = 0; mf < 2; mf++) {
                int r0 = rb * 32 + mf * 16 + g;
                ah[mf][0] = *(const unsigned*)&ash[r0][c0];
                ah[mf][1] = *(const unsigned*)&ash[r0 + 8][c0];
                ah[mf][2] = *(const unsigned*)&ash[r0][c0 + 8];
                ah[mf][3] = *(const unsigned*)&ash[r0 + 8][c0 + 8];
                al[mf][0] = *(const unsigned*)&asl[r0][c0];
                al[mf][1] = *(const unsigned*)&asl[r0 + 8][c0];
                al[mf][2] = *(const unsigned*)&asl[r0][c0 + 8];
                al[mf][3] = *(const unsigned*)&asl[r0 + 8][c0 + 8];
            }
#pragma unroll
            for (int j = 0; j < 8; j++) {
                uint4 B = g_bfrag_proj[(size_t)(k16 * 16 + cb * 8 + j) * 32 + lane];
#pragma unroll
                for (int mf = 0; mf < 2; mf++) {
                    float* d = acc[mf][j];
                    mma_bf16(d[0], d[1], d[2], d[3], ah[mf][0], ah[mf][1], ah[mf][2], ah[mf][3], B.x, B.y);
                    mma_bf16(d[0], d[1], d[2], d[3], al[mf][0], al[mf][1], al[mf][2], al[mf][3], B.x, B.y);
                    mma_bf16(d[0], d[1], d[2], d[3], ah[mf][0], ah[mf][1], ah[mf][2], ah[mf][3], B.z, B.w);
                }
            }
        }
        __syncthreads();
    }

    float* obase = cb ? g_dst : g_src;
#pragma unroll
    for (int mf = 0; mf < 2; mf++) {
        int r = n0 + rb * 32 + mf * 16 + g;
#pragma unroll
        for (int j = 0; j < 8; j++) {
            int c = j * 8 + 2 * t4;
            float* d = acc[mf][j];
            if (r < n)     *(float2*)&obase[(size_t)r * H + c]       = make_float2(d[0], d[1]);
            if (r + 8 < n) *(float2*)&obase[(size_t)(r + 8) * H + c] = make_float2(d[2], d[3]);
        }
    }
}

// =====================================================================
// Kernel B: edge MLP (tensor MMA) + max-free streaming softmax.
// R17: A fragments gathered DIRECTLY from global into registers in MMA
// layout (8 LDG.64/thread; each thread owns 2 edge rows x 4 float2
// chunks). Removes the staging tile, 8 STS + 16 LDS per thread, and 2
// of 4 block barriers. Invalid edges read row 0 (finite) and stay
// masked by vm in softmax -> valid outputs bit-identical.
// =====================================================================
__global__ void __launch_bounds__(256, 5)
edge_kernel(const float* __restrict__ ea,
            const int*   __restrict__ ei,
            const int*   __restrict__ nbr,
            int n)
{
    __shared__ __align__(16) float msgT[4][64][36];  // [local][ch][k] (+4 pad)
    __shared__ int      se_[4][KNB];
    __shared__ int      ss_[4][KNB];   // ei[e]*H (prescaled element offset)
    __shared__ unsigned smask[4];

    const int tid   = threadIdx.x;
    const int node0 = blockIdx.x * 4;

    if (tid < 128) {
        int local = tid >> 5, k = tid & 31;
        int node = node0 + local;
        int e = (node < n) ? nbr[(size_t)node * KNB + k] : -1;
        se_[local][k] = (e >= 0) ? e : 0;
        ss_[local][k] = (e >= 0) ? (ei[e] * H) : 0;
        unsigned msk = __ballot_sync(0xffffffffu, e >= 0);
        if (k == 0) smask[local] = msk;
    }
    __syncthreads();

    const int w8 = tid >> 5, lane = tid & 31;
    const int g = lane >> 2, t4 = lane & 3;
    const int loc = w8 >> 1;
    const int kk  = (w8 & 1) * 16 + g;   // this thread's r0 row within loc

    // direct gather of A fragments: 2 edge rows, 4 float2 chunks each
    unsigned ah[2][4], al[2][4];
    {
        const float* rowp0 = ea + (size_t)se_[loc][kk]     * EDGED;
        const float* rowp1 = ea + (size_t)se_[loc][kk + 8] * EDGED;
        float2 v[8];
#pragma unroll
        for (int ks = 0; ks < 2; ks++) {
            int c0 = ks * 16 + 2 * t4;
            v[ks * 4 + 0] = *(const float2*)&rowp0[c0];
            v[ks * 4 + 1] = *(const float2*)&rowp1[c0];
            v[ks * 4 + 2] = *(const float2*)&rowp0[c0 + 8];
            v[ks * 4 + 3] = *(const float2*)&rowp1[c0 + 8];
        }
#pragma unroll
        for (int ks = 0; ks < 2; ks++)
#pragma unroll
            for (int q = 0; q < 4; q++)
                ah[ks][q] = pack_split_hi(v[ks * 4 + q].x, v[ks * 4 + q].y, al[ks][q]);
    }

    // MMA phase: write results transposed into msgT[loc][ch][k]
    {
        float* base = &msgT[loc][0][0];
#pragma unroll
        for (int j = 0; j < 8; j++) {
            float d0 = 0.f, d1 = 0.f, d2 = 0.f, d3 = 0.f;
#pragma unroll
            for (int ks = 0; ks < 2; ks++) {
                uint4 B = g_bfrag_edge[(size_t)(ks * 8 + j) * 32 + lane];
                mma_bf16(d0, d1, d2, d3, ah[ks][0], ah[ks][1], ah[ks][2], ah[ks][3], B.x, B.y);
                mma_bf16(d0, d1, d2, d3, al[ks][0], al[ks][1], al[ks][2], al[ks][3], B.x, B.y);
                mma_bf16(d0, d1, d2, d3, ah[ks][0], ah[ks][1], ah[ks][2], ah[ks][3], B.z, B.w);
            }
            int c = j * 8 + 2 * t4;
            base[c * 36 + kk]           = d0;
            base[(c + 1) * 36 + kk]     = d1;
            base[c * 36 + kk + 8]       = d2;
            base[(c + 1) * 36 + kk + 8] = d3;
        }
    }
    __syncthreads();

    // max-free streaming softmax: thread = (local node, channel h),
    // vectorized msg reads (float4) + 4-way accumulators.
    {
        const int local = tid >> 6;
        const int h     = tid & 63;
        const int node  = node0 + local;
        const unsigned vm = smask[local];
        const float* row = &msgT[local][h][0];

        float den0 = 1e-16f, den1 = 0.f, den2 = 0.f, den3 = 0.f;
        float num0 = 0.f, num1 = 0.f, num2 = 0.f, num3 = 0.f;
#pragma unroll
        for (int kq = 0; kq < 8; kq++) {
            int k = kq * 4;
            float4 p = *(const float4*)&row[k];
            bool v0 = (vm >> k) & 1;
            bool v1 = (vm >> (k + 1)) & 1;
            bool v2 = (vm >> (k + 2)) & 1;
            bool v3 = (vm >> (k + 3)) & 1;
            float x0 = 0.f, x1 = 0.f, x2 = 0.f, x3 = 0.f;
            if (v0) x0 = g_src[(size_t)ss_[local][k]     + h];
            if (v1) x1 = g_src[(size_t)ss_[local][k + 1] + h];
            if (v2) x2 = g_src[(size_t)ss_[local][k + 2] + h];
            if (v3) x3 = g_src[(size_t)ss_[local][k + 3] + h];
            float m0 = fmaxf(p.x + x0, 0.f) + 1e-7f;
            float m1 = fmaxf(p.y + x1, 0.f) + 1e-7f;
            float m2 = fmaxf(p.z + x2, 0.f) + 1e-7f;
            float m3 = fmaxf(p.w + x3, 0.f) + 1e-7f;
            float a0 = v0 ? __expf(m0) : 0.f;
            float a1 = v1 ? __expf(m1) : 0.f;
            float a2 = v2 ? __expf(m2) : 0.f;
            float a3 = v3 ? __expf(m3) : 0.f;
            den0 += a0; den1 += a1; den2 += a2; den3 += a3;
            num0 = fmaf(m0, a0, num0);
            num1 = fmaf(m1, a1, num1);
            num2 = fmaf(m2, a2, num2);
            num3 = fmaf(m3, a3, num3);
        }

        if (node < n) {
            float dstf = g_dst[(size_t)node * H + h];
            float den = (den0 + den1) + (den2 + den3);
            float num = (num0 + num1) + (num2 + num3);
            g_out[(size_t)node * H + h] = num / den + dstf;
        }
    }
}

// =====================================================================
// Kernel C: g_h = g_out @ w1.T via tensor MMA + fused BN partial stats.
// =====================================================================
__global__ void __launch_bounds__(256)
mlp1_kernel(int n)
{
    __shared__ __align__(16) __nv_bfloat16 ash[128][72];
    __shared__ __align__(16) __nv_bfloat16 asl[128][72];
    __shared__ float rs [4][128];
    __shared__ float rs2[4][128];
    const int tid = threadIdx.x;
    const int warp = tid >> 5, lane = tid & 31;
    const int rb = warp >> 1, cb = warp & 1;
    const int g = lane >> 2, t4 = lane & 3;
    const int n0 = blockIdx.x * 128;

#pragma unroll
    for (int it = 0; it < 8; it++) {
        int i = tid + it * 256;
        int row = i >> 4, q = i & 15;
        int gn = n0 + row;
        float4 v = make_float4(0.f, 0.f, 0.f, 0.f);
        if (gn < n) v = *(const float4*)&g_out[(size_t)gn * H + q * 4];
        unsigned l0, l1;
        unsigned h0 = pack_split_hi(v.x, v.y, l0);
        unsigned h1 = pack_split_hi(v.z, v.w, l1);
        *(uint2*)&ash[row][q * 4] = make_uint2(h0, h1);
        *(uint2*)&asl[row][q * 4] = make_uint2(l0, l1);
    }
    __syncthreads();

    float acc[2][8][4];
#pragma unroll
    for (int mf = 0; mf < 2; mf++)
#pragma unroll
        for (int j = 0; j < 8; j++)
#pragma unroll
            for (int q = 0; q < 4; q++) acc[mf][j][q] = 0.f;

#pragma unroll
    for (int k16 = 0; k16 < 4; k16++) {
        int c0 = k16 * 16 + 2 * t4;
        unsigned ah[2][4], al[2][4];
#pragma unroll
        for (int mf = 0; mf < 2; mf++) {
            int r0 = rb * 32 + mf * 16 + g;
            ah[mf][0] = *(const unsigned*)&ash[r0][c0];
            ah[mf][1] = *(const unsigned*)&ash[r0 + 8][c0];
            ah[mf][2] = *(const unsigned*)&ash[r0][c0 + 8];
            ah[mf][3] = *(const unsigned*)&ash[r0 + 8][c0 + 8];
            al[mf][0] = *(const unsigned*)&asl[r0][c0];
            al[mf][1] = *(const unsigned*)&asl[r0 + 8][c0];
            al[mf][2] = *(const unsigned*)&asl[r0][c0 + 8];
            al[mf][3] = *(const unsigned*)&asl[r0 + 8][c0 + 8];
        }
#pragma unroll
        for (int j = 0; j < 8; j++) {
            uint4 B = g_bfrag_mlp1[(size_t)(k16 * 16 + cb * 8 + j) * 32 + lane];
#pragma unroll
            for (int mf = 0; mf < 2; mf++) {
                float* d = acc[mf][j];
                mma_bf16(d[0], d[1], d[2], d[3], ah[mf][0], ah[mf][1], ah[mf][2], ah[mf][3], B.x, B.y);
                mma_bf16(d[0], d[1], d[2], d[3], al[mf][0], al[mf][1], al[mf][2], al[mf][3], B.x, B.y);
                mma_bf16(d[0], d[1], d[2], d[3], ah[mf][0], ah[mf][1], ah[mf][2], ah[mf][3], B.z, B.w);
            }
        }
    }

#pragma unroll
    for (int mf = 0; mf < 2; mf++) {
        int r = n0 + rb * 32 + mf * 16 + g;
#pragma unroll
        for (int j = 0; j < 8; j++) {
            int c = cb * 64 + j * 8 + 2 * t4;
            float* d = acc[mf][j];
            if (r < n)     *(float2*)&g_h[(size_t)r * H2 + c]       = make_float2(d[0], d[1]);
            if (r + 8 < n) *(float2*)&g_h[(size_t)(r + 8) * H2 + c] = make_float2(d[2], d[3]);
        }
    }

#pragma unroll
    for (int j = 0; j < 8; j++) {
        float s0 = 0.f, s1 = 0.f, q0 = 0.f, q1 = 0.f;
#pragma unroll
        for (int mf = 0; mf < 2; mf++) {
            float* d = acc[mf][j];
            s0 += d[0] + d[2];
            s1 += d[1] + d[3];
            q0 += d[0] * d[0] + d[2] * d[2];
            q1 += d[1] * d[1] + d[3] * d[3];
        }
#pragma unroll
        for (int off = 4; off < 32; off <<= 1) {
            s0 += __shfl_xor_sync(0xffffffffu, s0, off);
            s1 += __shfl_xor_sync(0xffffffffu, s1, off);
            q0 += __shfl_xor_sync(0xffffffffu, q0, off);
            q1 += __shfl_xor_sync(0xffffffffu, q1, off);
        }
        if (g == 0) {
            int c = cb * 64 + j * 8 + 2 * t4;
            rs [rb][c]     = s0;
            rs [rb][c + 1] = s1;
            rs2[rb][c]     = q0;
            rs2[rb][c + 1] = q1;
        }
    }
    __syncthreads();
    if (tid < 128) {
        float s  = rs [0][tid] + rs [1][tid] + rs [2][tid] + rs [3][tid];
        float s2 = rs2[0][tid] + rs2[1][tid] + rs2[2][tid] + rs2[3][tid];
        g_part[(size_t)blockIdx.x * H2 + tid]                      = s;
        g_part[(size_t)NBMAX * H2 + (size_t)blockIdx.x * H2 + tid] = s2;
    }
}

// =====================================================================
// Kernel D: single-kernel BN fold. grid = 128, 512 threads, deterministic.
// =====================================================================
__global__ void __launch_bounds__(512)
fold_kernel(const float* __restrict__ gamma, const float* __restrict__ beta,
            int n, int nb)
{
    __shared__ float sh[512], sh2[512];
    const int c = blockIdx.x;
    const int t = threadIdx.x;
    float s = 0.f, s2 = 0.f;
    if (t < nb) {
        s  = g_part[(size_t)t * H2 + c];
        s2 = g_part[(size_t)NBMAX * H2 + (size_t)t * H2 + c];
    }
    sh[t] = s; sh2[t] = s2;
    __syncthreads();
#pragma unroll
    for (int off = 256; off > 0; off >>= 1) {
        if (t < off) { sh[t] += sh[t + off]; sh2[t] += sh2[t + off]; }
        __syncthreads();
    }
    if (t == 0) {
        float inv_n = 1.f / (float)n;
        float mean  = sh[0] * inv_n;
        float var   = sh2[0] * inv_n - mean * mean;
        float sc    = gamma[c] * rsqrtf(var + 1e-5f);
        g_sb[c]      = sc;
        g_sb[H2 + c] = beta[c] - mean * sc;
    }
}

// =====================================================================
// Kernel E: out = relu(bn(g_h)) @ w2.T via tensor MMA. tile 128 x 64.
// =====================================================================
__global__ void __launch_bounds__(256)
mlp2_kernel(float* __restrict__ outp, int n)
{
    __shared__ __align__(16) __nv_bfloat16 ash[128][40];
    __shared__ __align__(16) __nv_bfloat16 asl[128][40];
    const int tid = threadIdx.x;
    const int warp = tid >> 5, lane = tid & 31;
    const int rb = warp >> 1, cb = warp & 1;
    const int g = lane >> 2, t4 = lane & 3;
    const int n0 = blockIdx.x * 128;

    float acc[2][4][4];
#pragma unroll
    for (int mf = 0; mf < 2; mf++)
#pragma unroll
        for (int j = 0; j < 4; j++)
#pragma unroll
            for (int q = 0; q < 4; q++) acc[mf][j][q] = 0.f;

    for (int dt = 0; dt < 128; dt += 32) {
#pragma unroll
        for (int it = 0; it < 4; it++) {
            int i = tid + it * 256;
            int row = i >> 3, q = i & 7;
            int gn = n0 + row;
            int d  = dt + q * 4;
            float4 v = make_float4(0.f, 0.f, 0.f, 0.f);
            if (gn < n) v = *(const float4*)&g_h[(size_t)gn * H2 + d];
            float4 sc = *(const float4*)&g_sb[d];
            float4 bi = *(const float4*)&g_sb[H2 + d];
            float r0 = fmaxf(fmaf(v.x, sc.x, bi.x), 0.f);
            float r1 = fmaxf(fmaf(v.y, sc.y, bi.y), 0.f);
            float r2 = fmaxf(fmaf(v.z, sc.z, bi.z), 0.f);
            float r3 = fmaxf(fmaf(v.w, sc.w, bi.w), 0.f);
            unsigned l0, l1;
            unsigned h0 = pack_split_hi(r0, r1, l0);
            unsigned h1 = pack_split_hi(r2, r3, l1);
            *(uint2*)&ash[row][q * 4] = make_uint2(h0, h1);
            *(uint2*)&asl[row][q * 4] = make_uint2(l0, l1);
        }
        __syncthreads();

#pragma unroll
        for (int ks = 0; ks < 2; ks++) {
            int k16 = (dt >> 4) + ks;
            int c0 = ks * 16 + 2 * t4;
            unsigned ah[2][4], al[2][4];
#pragma unroll
            for (int mf = 0; mf < 2; mf++) {
                int r0 = rb * 32 + mf * 16 + g;
                ah[mf][0] = *(const unsigned*)&ash[r0][c0];
                ah[mf][1] = *(const unsigned*)&ash[r0 + 8][c0];
                ah[mf][2] = *(const unsigned*)&ash[r0][c0 + 8];
                ah[mf][3] = *(const unsigned*)&ash[r0 + 8][c0 + 8];
                al[mf][0] = *(const unsigned*)&asl[r0][c0];
                al[mf][1] = *(const unsigned*)&asl[r0 + 8][c0];
                al[mf][2] = *(const unsigned*)&asl[r0][c0 + 8];
                al[mf][3] = *(const unsigned*)&asl[r0 + 8][c0 + 8];
            }
#pragma unroll
            for (int j = 0; j < 4; j++) {
                uint4 B = g_bfrag_mlp2[(size_t)(k16 * 8 + cb * 4 + j) * 32 + lane];
#pragma unroll
                for (int mf = 0; mf < 2; mf++) {
                    float* d = acc[mf][j];
                    mma_bf16(d[0], d[1], d[2], d[3], ah[mf][0], ah[mf][1], ah[mf][2], ah[mf][3], B.x, B.y);
                    mma_bf16(d[0], d[1], d[2], d[3], al[mf][0], al[mf][1], al[mf][2], al[mf][3], B.x, B.y);
                    mma_bf16(d[0], d[1], d[2], d[3], ah[mf][0], ah[mf][1], ah[mf][2], ah[mf][3], B.z, B.w);
                }
            }
        }
        __syncthreads();
    }

#pragma unroll
    for (int mf = 0; mf < 2; mf++) {
        int r = n0 + rb * 32 + mf * 16 + g;
#pragma unroll
        for (int j = 0; j < 4; j++) {
            int c = cb * 32 + j * 8 + 2 * t4;
            float* d = acc[mf][j];
            if (r < n)     *(float2*)&outp[(size_t)r * H + c]       = make_float2(d[0], d[1]);
            if (r + 8 < n) *(float2*)&outp[(size_t)(r + 8) * H + c] = make_float2(d[2], d[3]);
        }
    }
}

// =====================================================================
extern "C" void kernel_launch(void* const* d_in, const int* in_sizes, int n_in,
                              void* d_out, int out_size)
{
    const float* x      = (const float*)d_in[0];
    const float* ea     = (const float*)d_in[1];
    const float* w_src  = (const float*)d_in[2];
    const float* w_dst  = (const float*)d_in[3];
    const float* w_edge = (const float*)d_in[4];
    const float* w1     = (const float*)d_in[5];
    const float* gamma  = (const float*)d_in[6];
    const float* beta   = (const float*)d_in[7];
    const float* w2     = (const float*)d_in[8];
    const int*   ei     = (const int*)d_in[9];
    const int*   nbr    = (const int*)d_in[10];
    float* outp = (float*)d_out;

    int n = in_sizes[0] / INC;
    if (n > MAXN) n = MAXN;

    int gb128 = (n + 127) / 128;
    prep_a_kernel<<<24, 256>>>(w_src, w_dst, w1);        // launch 1
    proj_kernel  <<<gb128, 256>>>(x, n);                 // launch 2
    prep_b_kernel<<<10, 256>>>(w_edge, w2);              // launch 3
    edge_kernel  <<<(n + 3) / 4, 256>>>(ea, ei, nbr, n); // launch 4 (profiled)
    mlp1_kernel  <<<gb128, 256>>>(n);                    // launch 5
    fold_kernel  <<<128, 512>>>(gamma, beta, n, gb128);  // launch 6
    mlp2_kernel  <<<gb128, 256>>>(outp, n);              // launch 7
}